// round 15
// baseline (speedup 1.0000x reference)
#include <cuda_runtime.h>
#include <cuda_fp16.h>
#include <math.h>
#include <stdint.h>
#include <string.h>

// ---------------------------------------------------------------------------
// SiT block: B=8, N=1024, C=1024, H=16, HD=64, MLP=4096
// Round 15: R14 + persistent proj/fc2 GEMMs (shift-only indexing, 296 CTAs,
// continuous 3-stage ring). qkv/fc1/FA/aux unchanged from R14.
// ---------------------------------------------------------------------------

#define Bq 8
#define Nq 1024
#define Cq 1024
#define MLPq 4096
#define TOK (Bq * Nq)
#define MODW (6 * Cq)
#define STAGES 3
#define BKH 64
#define ROWB 144
#define PGRID 296

// ----------------------------- scratch (static) ----------------------------
__device__ float  g_silu_c[Bq * Cq];
__device__ float  g_mod[Bq * MODW];
__device__ float  g_fmask[Bq * Nq];
__device__ int    g_lenq[Bq];
__device__ float  g_sumv[128 * 64];
__device__ float  g_x2[TOK * Cq];
__device__ __half g_h16[TOK * Cq];
__device__ __half g_qkv16[TOK * 3 * Cq];
__device__ __half g_vt16[128 * 64 * 1024];
__device__ __half g_attn16[TOK * Cq];
__device__ __half g_t16[TOK * MLPq];
__device__ __half g_qkvw16[3 * Cq * Cq];
__device__ __half g_projw16[Cq * Cq];
__device__ __half g_fc1w16[MLPq * Cq];
__device__ __half g_fc2w16[Cq * MLPq];

// ----------------------------- helpers -------------------------------------
__device__ __forceinline__ uint32_t smem_u32(const void* p) {
    uint32_t a;
    asm("{ .reg .u64 t; cvta.to.shared.u64 t, %1; cvt.u32.u64 %0, t; }" : "=r"(a) : "l"(p));
    return a;
}
__device__ __forceinline__ void cp16(uint32_t dst, const void* src) {
    asm volatile("cp.async.cg.shared.global [%0], [%1], 16;" :: "r"(dst), "l"(src));
}
__device__ __forceinline__ void cp_commit() {
    asm volatile("cp.async.commit_group;" ::: "memory");
}
template <int N>
__device__ __forceinline__ void cp_wait() {
    asm volatile("cp.async.wait_group %0;" :: "n"(N) : "memory");
}
__device__ __forceinline__ void ldsm4(uint32_t* r, uint32_t addr) {
    asm volatile("ldmatrix.sync.aligned.m8n8.x4.shared.b16 {%0,%1,%2,%3}, [%4];"
        : "=r"(r[0]), "=r"(r[1]), "=r"(r[2]), "=r"(r[3]) : "r"(addr));
}
__device__ __forceinline__ void mma16(float* c, const uint32_t* a, const uint32_t* b) {
    asm volatile("mma.sync.aligned.m16n8k16.row.col.f32.f16.f16.f32 "
        "{%0,%1,%2,%3}, {%4,%5,%6,%7}, {%8,%9}, {%0,%1,%2,%3};"
        : "+f"(c[0]), "+f"(c[1]), "+f"(c[2]), "+f"(c[3])
        : "r"(a[0]), "r"(a[1]), "r"(a[2]), "r"(a[3]), "r"(b[0]), "r"(b[1]));
}
__device__ __forceinline__ uint32_t packh2(float lo, float hi) {
    __half2 h = __floats2half2_rn(lo, hi);
    uint32_t u; memcpy(&u, &h, 4); return u;
}
__device__ __forceinline__ float gelu_tanh(float x) {
    float x3 = x * x * x;
    return 0.5f * x * (1.0f + tanhf(0.7978845608028654f * (x + 0.044715f * x3)));
}

// ---------------------------------------------------------------------------
// fp16 NT GEMM (R10 config) for qkv/fc1: 128x128 CTA / 128 thr / warp 64x64.
// SKIP=1: skip tiles with n0 < 2048 whose 128 M-rows are all padded.
// ---------------------------------------------------------------------------
template <int EPI, int SKIP, typename OT>
__global__ __launch_bounds__(128, 2)
void gemm_h(const __half* __restrict__ A, const __half* __restrict__ B,
            const float* __restrict__ bias, const float* __restrict__ resid,
            const float* __restrict__ mod, int gate_ofs,
            OT* __restrict__ C, const int* __restrict__ lenq,
            int lda, int ldb, int ldc, int K) {
    constexpr int A_BY = 128 * ROWB;
    constexpr int STAGE_BY = 2 * A_BY;
    constexpr int M16 = 4, N8 = 8;

    extern __shared__ char dsm[];
    uint32_t sbase = smem_u32(dsm);
    int tid = threadIdx.x;
    int wid = tid >> 5, lane = tid & 31;
    int warpM = wid >> 1, warpN = wid & 1;
    int qid = lane >> 2, tq = lane & 3;

    int m0 = blockIdx.y * 128;
    int n0 = blockIdx.x * 128;

    if (SKIP) {
        if (n0 < 2048 && (m0 & 1023) >= lenq[m0 >> 10]) return;
    }

    float c[M16][N8][4];
#pragma unroll
    for (int i = 0; i < M16; i++)
#pragma unroll
        for (int j = 0; j < N8; j++)
#pragma unroll
            for (int q = 0; q < 4; q++) c[i][j][q] = 0.f;

    auto load_stage = [&](int st, int ks) {
        uint32_t ao = sbase + st * STAGE_BY;
        uint32_t bo = ao + A_BY;
        int k0 = ks * BKH;
#pragma unroll
        for (int j = 0; j < 8; j++) {
            int i = tid + j * 128;
            int r = i >> 3, ch = i & 7;
            cp16(ao + r * ROWB + ch * 16,
                 A + (size_t)(m0 + r) * lda + k0 + ch * 8);
        }
#pragma unroll
        for (int j = 0; j < 8; j++) {
            int i = tid + j * 128;
            int r = i >> 3, ch = i & 7;
            cp16(bo + r * ROWB + ch * 16,
                 B + (size_t)(n0 + r) * ldb + k0 + ch * 8);
        }
    };

    int kslabs = K / BKH;
    load_stage(0, 0); cp_commit();
    load_stage(1, 1); cp_commit();

    int aRow = lane & 15, aCol = (lane >> 4) * 16;
    int bRow = (lane & 7) + ((lane >> 4) << 3), bCol = ((lane >> 3) & 1) * 16;

    uint32_t af[2][M16][4];
    uint32_t bf[2][N8][2];

    auto load_frags = [&](uint32_t aBase, uint32_t bBase, int koff, int buf) {
#pragma unroll
        for (int m16 = 0; m16 < M16; m16++)
            ldsm4(af[buf][m16], aBase + (warpM * 64 + m16 * 16 + aRow) * ROWB + koff + aCol);
#pragma unroll
        for (int p = 0; p < N8 / 2; p++) {
            uint32_t r4[4];
            ldsm4(r4, bBase + (warpN * 64 + p * 16 + bRow) * ROWB + koff + bCol);
            bf[buf][2 * p][0] = r4[0]; bf[buf][2 * p][1] = r4[1];
            bf[buf][2 * p + 1][0] = r4[2]; bf[buf][2 * p + 1][1] = r4[3];
        }
    };

    for (int k = 0; k < kslabs; k++) {
        cp_wait<1>();
        __syncthreads();
        int kn = k + 2;
        if (kn < kslabs) load_stage(kn % STAGES, kn);
        cp_commit();

        uint32_t aBase = sbase + (k % STAGES) * STAGE_BY;
        uint32_t bBase = aBase + A_BY;

        load_frags(aBase, bBase, 0, 0);
#pragma unroll
        for (int ks = 0; ks < 4; ks++) {
            int cur = ks & 1;
            if (ks < 3) load_frags(aBase, bBase, (ks + 1) * 32, cur ^ 1);
#pragma unroll
            for (int m16 = 0; m16 < M16; m16++)
#pragma unroll
                for (int n8 = 0; n8 < N8; n8++)
                    mma16(c[m16][n8], af[cur][m16], bf[cur][n8]);
        }
    }

#pragma unroll
    for (int m16 = 0; m16 < M16; m16++) {
#pragma unroll
        for (int hh = 0; hh < 2; hh++) {
            int gr = m0 + warpM * 64 + m16 * 16 + hh * 8 + qid;
#pragma unroll
            for (int n8 = 0; n8 < N8; n8++) {
                int gcol = n0 + warpN * 64 + n8 * 8 + tq * 2;
                float v0 = c[m16][n8][hh * 2 + 0];
                float v1 = c[m16][n8][hh * 2 + 1];
                {
                    float2 b2 = *(const float2*)&bias[gcol];
                    v0 += b2.x; v1 += b2.y;
                }
                if (EPI == 1) { v0 = gelu_tanh(v0); v1 = gelu_tanh(v1); }
                OT* dst = &C[(size_t)gr * ldc + gcol];
                if (sizeof(OT) == 2) {
                    __half2 hv = __floats2half2_rn(v0, v1);
                    *(__half2*)dst = hv;
                } else {
                    *(float2*)dst = make_float2(v0, v1);
                }
            }
        }
    }
}

// ---------------------------------------------------------------------------
// Persistent fp16 NT GEMM for proj/fc2 (EPI2): 296 CTAs, 256 thr, warp 64x32.
// Shift-only indexing: kslabs = 1<<LOGK; tile -> m0=(tile&63)<<7, n0=(tile>>6)<<7.
// Continuous 3-stage ring across tiles (no drain); epilogue overlaps prefetch.
// ---------------------------------------------------------------------------
template <int LOGK>
__global__ __launch_bounds__(256, 2)
void gemm_pp(const __half* __restrict__ A, const __half* __restrict__ B,
             const float* __restrict__ bias, const float* __restrict__ resid,
             const float* __restrict__ mod, int gate_ofs,
             float* __restrict__ C,
             int lda, int ldb, int ldc, int nt) {
    constexpr int KS = 1 << LOGK;
    constexpr int A_BY = 128 * ROWB;
    constexpr int STAGE_BY = 2 * A_BY;
    constexpr int M16 = 4, N8 = 4;     // warp 64x32

    extern __shared__ char dsm[];
    uint32_t sbase = smem_u32(dsm);
    int tid = threadIdx.x;
    int wid = tid >> 5, lane = tid & 31;
    int warpN = wid & 3, warpM = wid >> 2;
    int qid = lane >> 2, tq = lane & 3;
    int bid = blockIdx.x;

    int myTiles = (nt - bid + PGRID - 1) / PGRID;
    if (myTiles <= 0) return;
    int total = myTiles << LOGK;

    auto load_g = [&](int st, int g) {
        if (g >= total) return;
        int tm = g >> LOGK;
        int ks = g & (KS - 1);
        int tile = bid + tm * PGRID;
        int m0 = (tile & 63) << 7;
        int n0 = (tile >> 6) << 7;
        uint32_t ao = sbase + st * STAGE_BY;
        uint32_t bo = ao + A_BY;
        int k0 = ks << 6;                  // *BKH
#pragma unroll
        for (int j = 0; j < 4; j++) {
            int i = tid + j * 256;
            int r = i >> 3, ch = i & 7;
            cp16(ao + r * ROWB + ch * 16,
                 A + (size_t)(m0 + r) * lda + k0 + ch * 8);
        }
#pragma unroll
        for (int j = 0; j < 4; j++) {
            int i = tid + j * 256;
            int r = i >> 3, ch = i & 7;
            cp16(bo + r * ROWB + ch * 16,
                 B + (size_t)(n0 + r) * ldb + k0 + ch * 8);
        }
    };

    load_g(0, 0); cp_commit();
    load_g(1, 1); cp_commit();

    int aRow = lane & 15, aCol = (lane >> 4) * 16;
    int bRow = (lane & 7) + ((lane >> 4) << 3), bCol = ((lane >> 3) & 1) * 16;

    int g = 0;
    int stC = 0, stL = 2;                  // compute stage, load-target stage
    for (int tm = 0; tm < myTiles; tm++) {
        int tile = bid + tm * PGRID;
        int m0 = (tile & 63) << 7;
        int n0 = (tile >> 6) << 7;

        float c[M16][N8][4];
#pragma unroll
        for (int i = 0; i < M16; i++)
#pragma unroll
            for (int j = 0; j < N8; j++)
#pragma unroll
                for (int q = 0; q < 4; q++) c[i][j][q] = 0.f;

        for (int ks0 = 0; ks0 < KS; ks0++, g++) {
            cp_wait<1>();
            __syncthreads();
            load_g(stL, g + 2);
            cp_commit();

            uint32_t aBase = sbase + stC * STAGE_BY;
            uint32_t bBase = aBase + A_BY;
#pragma unroll
            for (int ks = 0; ks < 4; ks++) {
                int koff = ks * 32;
                uint32_t af[M16][4];
#pragma unroll
                for (int m16 = 0; m16 < M16; m16++)
                    ldsm4(af[m16], aBase + (warpM * 64 + m16 * 16 + aRow) * ROWB + koff + aCol);
                uint32_t bf[N8][2];
#pragma unroll
                for (int p = 0; p < N8 / 2; p++) {
                    uint32_t r4[4];
                    ldsm4(r4, bBase + (warpN * 32 + p * 16 + bRow) * ROWB + koff + bCol);
                    bf[2 * p][0] = r4[0]; bf[2 * p][1] = r4[1];
                    bf[2 * p + 1][0] = r4[2]; bf[2 * p + 1][1] = r4[3];
                }
#pragma unroll
                for (int m16 = 0; m16 < M16; m16++)
#pragma unroll
                    for (int n8 = 0; n8 < N8; n8++)
                        mma16(c[m16][n8], af[m16], bf[n8]);
            }
            stC = (stC == 2) ? 0 : stC + 1;
            stL = (stL == 2) ? 0 : stL + 1;
        }

        // epilogue (resid + gate*(+bias)) — overlaps next tile's prefetch
#pragma unroll
        for (int m16 = 0; m16 < M16; m16++) {
#pragma unroll
            for (int hh = 0; hh < 2; hh++) {
                int gr = m0 + warpM * 64 + m16 * 16 + hh * 8 + qid;
#pragma unroll
                for (int n8 = 0; n8 < N8; n8++) {
                    int gcol = n0 + warpN * 32 + n8 * 8 + tq * 2;
                    float v0 = c[m16][n8][hh * 2 + 0];
                    float v1 = c[m16][n8][hh * 2 + 1];
                    float2 b2 = *(const float2*)&bias[gcol];
                    v0 += b2.x; v1 += b2.y;
                    float2 g2 = *(const float2*)&mod[(size_t)(gr >> 10) * MODW + gate_ofs + gcol];
                    float2 r2 = *(const float2*)&resid[(size_t)gr * ldc + gcol];
                    v0 = r2.x + g2.x * v0;
                    v1 = r2.y + g2.y * v1;
                    *(float2*)&C[(size_t)gr * ldc + gcol] = make_float2(v0, v1);
                }
            }
        }
    }
}

// ---------------------------------------------------------------------------
// Fused flash attention (R14): 128-thr CTA / 64 q rows / 2-stage KV ring /
// dead q-tile short-circuit.
// ---------------------------------------------------------------------------
#define FA_QOFF 0
#define FA_FOFF 9216
#define FA_KOFF 13312
#define FA_KST  18432
#define FA_VOFF 50176
#define FA_VST  17408
#define FA_SMEM 84992

__global__ __launch_bounds__(128, 2)
void fa_kernel(const __half* __restrict__ qkv, const __half* __restrict__ vt,
               const float* __restrict__ fmask, const float* __restrict__ sumv,
               __half* __restrict__ attn) {
    extern __shared__ char dsm[];
    __shared__ float sred[4];
    __shared__ int s_nt;
    uint32_t sb = smem_u32(dsm);
    const float* smF = (const float*)(dsm + FA_FOFF);
    int tid = threadIdx.x, wid = tid >> 5, lane = tid & 31;
    int qid = lane >> 2, tq = lane & 3;
    int by = blockIdx.y;
    int b = by >> 4, h = by & 15;
    int q0 = blockIdx.x * 64;

    if (fmask[b * 1024 + q0] == 0.f) {
        const float* sv = sumv + by * 64;
        int gr0 = q0 + wid * 16 + qid;
        __half* o0 = attn + ((size_t)(b * 1024) + gr0) * 1024 + h * 64;
        __half* o1 = o0 + (size_t)8 * 1024;
#pragma unroll
        for (int t = 0; t < 8; t++) {
            float2 s2 = *(const float2*)&sv[8 * t + 2 * tq];
            __half2 hv = __floats2half2_rn(s2.x * (1.f / 1024.f), s2.y * (1.f / 1024.f));
            *(__half2*)(o0 + 8 * t + 2 * tq) = hv;
            *(__half2*)(o1 + 8 * t + 2 * tq) = hv;
        }
        return;
    }

    const __half* Qg = qkv + ((size_t)(b * 1024 + q0)) * 3072 + h * 64;
    const __half* Kg = qkv + ((size_t)(b * 1024)) * 3072 + 1024 + h * 64;
    const __half* Vg = vt + (size_t)by * 64 * 1024;

    auto loadKV = [&](int st, int kt) {
#pragma unroll
        for (int j = 0; j < 8; j++) {
            int i = tid + j * 128;
            int r = i >> 3, ch = i & 7;
            cp16(sb + FA_KOFF + st * FA_KST + r * 144 + ch * 16,
                 Kg + (size_t)(kt * 128 + r) * 3072 + ch * 8);
        }
#pragma unroll
        for (int j = 0; j < 8; j++) {
            int i = tid + j * 128;
            int r = i >> 4, ch = i & 15;
            cp16(sb + FA_VOFF + st * FA_VST + r * 272 + ch * 16,
                 Vg + (size_t)r * 1024 + kt * 128 + ch * 8);
        }
    };

#pragma unroll
    for (int j = 0; j < 4; j++) {
        int i = tid + j * 128;
        int r = i >> 3, ch = i & 7;
        cp16(sb + FA_QOFF + r * 144 + ch * 16, Qg + (size_t)r * 3072 + ch * 8);
    }
    cp16(sb + FA_FOFF + tid * 32, fmask + b * 1024 + tid * 8);
    cp16(sb + FA_FOFF + tid * 32 + 16, fmask + b * 1024 + tid * 8 + 4);
    loadKV(0, 0);
    cp_commit();

    int aRow = lane & 15, aCol = (lane >> 4) * 16;
    int bRow = (lane & 7) + ((lane >> 4) << 3), bCol = ((lane >> 3) & 1) * 16;
    int r0 = wid * 16;

    cp_wait<0>();
    __syncthreads();

    {
        float cnt = 0.f;
        float4 m4a = *(const float4*)(smF + tid * 8);
        float4 m4b = *(const float4*)(smF + tid * 8 + 4);
        cnt = (m4a.x != 0.f) + (m4a.y != 0.f) + (m4a.z != 0.f) + (m4a.w != 0.f)
            + (m4b.x != 0.f) + (m4b.y != 0.f) + (m4b.z != 0.f) + (m4b.w != 0.f);
#pragma unroll
        for (int o = 16; o > 0; o >>= 1) cnt += __shfl_down_sync(0xFFFFFFFFu, cnt, o);
        if (lane == 0) sred[wid] = cnt;
        __syncthreads();
        if (tid == 0) {
            float tot = sred[0] + sred[1] + sred[2] + sred[3];
            s_nt = ((int)(tot + 0.5f) + 127) >> 7;
        }
        __syncthreads();
    }
    int ntiles = s_nt;

    uint32_t qa[4][4];
#pragma unroll
    for (int ks = 0; ks < 4; ks++)
        ldsm4(qa[ks], sb + FA_QOFF + (r0 + aRow) * 144 + ks * 32 + aCol);

    float O[8][4];
#pragma unroll
    for (int t = 0; t < 8; t++)
#pragma unroll
        for (int q = 0; q < 4; q++) O[t][q] = 0.f;
    float m0 = -3.0e38f, m1 = -3.0e38f, l0 = 0.f, l1 = 0.f;

    for (int kt = 0; kt < ntiles; kt++) {
        if (kt > 0) { cp_wait<0>(); __syncthreads(); }
        if (kt + 1 < ntiles) loadKV((kt + 1) & 1, kt + 1);
        cp_commit();

        uint32_t Ks = sb + FA_KOFF + (kt & 1) * FA_KST;
        uint32_t Vs = sb + FA_VOFF + (kt & 1) * FA_VST;

        float sc[16][4];
#pragma unroll
        for (int j = 0; j < 16; j++)
#pragma unroll
            for (int q = 0; q < 4; q++) sc[j][q] = 0.f;
#pragma unroll
        for (int ks = 0; ks < 4; ks++) {
            uint32_t kb[16][2];
#pragma unroll
            for (int p = 0; p < 8; p++) {
                uint32_t r4[4];
                ldsm4(r4, Ks + (16 * p + bRow) * 144 + ks * 32 + bCol);
                kb[2 * p][0] = r4[0]; kb[2 * p][1] = r4[1];
                kb[2 * p + 1][0] = r4[2]; kb[2 * p + 1][1] = r4[3];
            }
#pragma unroll
            for (int j = 0; j < 16; j++) mma16(sc[j], qa[ks], kb[j]);
        }

        bool mr0 = smF[q0 + r0 + qid] != 0.f;
        bool mr1 = smF[q0 + r0 + qid + 8] != 0.f;
#pragma unroll
        for (int j = 0; j < 16; j++) {
            int kvc = kt * 128 + 8 * j + 2 * tq;
            bool mk0 = smF[kvc] != 0.f;
            bool mk1 = smF[kvc + 1] != 0.f;
            sc[j][0] = (mr0 && mk0) ? sc[j][0] * 0.125f : -1e9f;
            sc[j][1] = (mr0 && mk1) ? sc[j][1] * 0.125f : -1e9f;
            sc[j][2] = (mr1 && mk0) ? sc[j][2] * 0.125f : -1e9f;
            sc[j][3] = (mr1 && mk1) ? sc[j][3] * 0.125f : -1e9f;
        }

        float mx0 = -3.0e38f, mx1 = -3.0e38f;
#pragma unroll
        for (int j = 0; j < 16; j++) {
            mx0 = fmaxf(mx0, fmaxf(sc[j][0], sc[j][1]));
            mx1 = fmaxf(mx1, fmaxf(sc[j][2], sc[j][3]));
        }
        mx0 = fmaxf(mx0, __shfl_xor_sync(0xFFFFFFFFu, mx0, 1));
        mx0 = fmaxf(mx0, __shfl_xor_sync(0xFFFFFFFFu, mx0, 2));
        mx1 = fmaxf(mx1, __shfl_xor_sync(0xFFFFFFFFu, mx1, 1));
        mx1 = fmaxf(mx1, __shfl_xor_sync(0xFFFFFFFFu, mx1, 2));
        float nm0 = fmaxf(m0, mx0), nm1 = fmaxf(m1, mx1);
        float cr0 = __expf(m0 - nm0), cr1 = __expf(m1 - nm1);
        m0 = nm0; m1 = nm1;
        float rs0 = 0.f, rs1 = 0.f;
#pragma unroll
        for (int j = 0; j < 16; j++) {
            sc[j][0] = __expf(sc[j][0] - m0);
            sc[j][1] = __expf(sc[j][1] - m0);
            sc[j][2] = __expf(sc[j][2] - m1);
            sc[j][3] = __expf(sc[j][3] - m1);
            rs0 += sc[j][0] + sc[j][1];
            rs1 += sc[j][2] + sc[j][3];
        }
        rs0 += __shfl_xor_sync(0xFFFFFFFFu, rs0, 1);
        rs0 += __shfl_xor_sync(0xFFFFFFFFu, rs0, 2);
        rs1 += __shfl_xor_sync(0xFFFFFFFFu, rs1, 1);
        rs1 += __shfl_xor_sync(0xFFFFFFFFu, rs1, 2);
        l0 = l0 * cr0 + rs0;
        l1 = l1 * cr1 + rs1;
#pragma unroll
        for (int t = 0; t < 8; t++) {
            O[t][0] *= cr0; O[t][1] *= cr0;
            O[t][2] *= cr1; O[t][3] *= cr1;
        }

        uint32_t pa[8][4];
#pragma unroll
        for (int k = 0; k < 8; k++) {
            pa[k][0] = packh2(sc[2 * k][0], sc[2 * k][1]);
            pa[k][1] = packh2(sc[2 * k][2], sc[2 * k][3]);
            pa[k][2] = packh2(sc[2 * k + 1][0], sc[2 * k + 1][1]);
            pa[k][3] = packh2(sc[2 * k + 1][2], sc[2 * k + 1][3]);
        }

#pragma unroll
        for (int k = 0; k < 8; k++) {
            uint32_t vb[8][2];
#pragma unroll
            for (int p = 0; p < 4; p++) {
                uint32_t r4[4];
                ldsm4(r4, Vs + (16 * p + bRow) * 272 + k * 32 + bCol);
                vb[2 * p][0] = r4[0]; vb[2 * p][1] = r4[1];
                vb[2 * p + 1][0] = r4[2]; vb[2 * p + 1][1] = r4[3];
            }
#pragma unroll
            for (int t = 0; t < 8; t++) mma16(O[t], pa[k], vb[t]);
        }
    }

    bool mr0 = smF[q0 + r0 + qid] != 0.f;
    bool mr1 = smF[q0 + r0 + qid + 8] != 0.f;
    float li0 = 1.f / l0, li1 = 1.f / l1;
    int gr0 = q0 + r0 + qid;
    __half* o0 = attn + ((size_t)(b * 1024) + gr0) * 1024 + h * 64;
    __half* o1 = o0 + (size_t)8 * 1024;
    const float* sv = sumv + by * 64;
#pragma unroll
    for (int t = 0; t < 8; t++) {
        float2 s2 = *(const float2*)&sv[8 * t + 2 * tq];
        float u0 = mr0 ? O[t][0] * li0 : s2.x * (1.f / 1024.f);
        float u1 = mr0 ? O[t][1] * li0 : s2.y * (1.f / 1024.f);
        float u2 = mr1 ? O[t][2] * li1 : s2.x * (1.f / 1024.f);
        float u3 = mr1 ? O[t][3] * li1 : s2.y * (1.f / 1024.f);
        *(__half2*)(o0 + 8 * t + 2 * tq) = __floats2half2_rn(u0, u1);
        *(__half2*)(o1 + 8 * t + 2 * tq) = __floats2half2_rn(u2, u3);
    }
}

// ---------------------------------------------------------------------------
// Merged weight conversion + prep + sumv zeroing + length accumulation
// ---------------------------------------------------------------------------
#define CV_Q 1572864
#define CV_P (CV_Q + 524288)
#define CV_F1 (CV_P + 2097152)
#define CV_TOT (CV_F1 + 2097152)

__global__ void cvt_all(const float* __restrict__ qkv_w, const float* __restrict__ proj_w,
                        const float* __restrict__ fc1_w, const float* __restrict__ fc2_w,
                        __half* __restrict__ o_qkv, __half* __restrict__ o_proj,
                        __half* __restrict__ o_fc1, __half* __restrict__ o_fc2,
                        const float* __restrict__ c, const void* __restrict__ mask,
                        float* __restrict__ silu_c, float* __restrict__ fmask,
                        float* __restrict__ sumv, int* __restrict__ lenq) {
    int i = blockIdx.x * blockDim.x + threadIdx.x;
    if (i < 128 * 64) sumv[i] = 0.f;
    if (i < Bq * Cq) {
        float v = c[i];
        silu_c[i] = v / (1.0f + expf(-v));
        unsigned w0 = *(const unsigned*)mask;
        float mv;
        if (w0 == 0x3F800000u)        mv = ((const float*)mask)[i];
        else if (w0 == 0x01010101u)   mv = ((const unsigned char*)mask)[i] ? 1.f : 0.f;
        else                          mv = ((const int*)mask)[i] ? 1.f : 0.f;
        bool on = (mv != 0.f);
        fmask[i] = on ? 1.f : 0.f;
        if (on) atomicAdd(&lenq[i >> 10], 1);
    }
    if (i >= CV_TOT) return;
    const float* s; __half* d; int off;
    if (i < CV_Q)        { s = qkv_w;  d = o_qkv;  off = i; }
    else if (i < CV_P)   { s = proj_w; d = o_proj; off = i - CV_Q; }
    else if (i < CV_F1)  { s = fc1_w;  d = o_fc1;  off = i - CV_P; }
    else                 { s = fc2_w;  d = o_fc2;  off = i - CV_F1; }
    float2 v = *(const float2*)&s[off * 2];
    *(__half2*)&d[off * 2] = __floats2half2_rn(v.x, v.y);
}

// ---------------------------------------------------------------------------
// fp32 SGEMM for the tiny ada GEMM (M=8)
// ---------------------------------------------------------------------------
__global__ __launch_bounds__(256)
void sgemm_ada(const float* __restrict__ A, const float* __restrict__ B,
               const float* __restrict__ bias, float* __restrict__ C,
               int M, int N, int K) {
    __shared__ float As[16][128];
    __shared__ float Bs[16][128];
    int tid = threadIdx.x;
    int tx = tid & 15, ty = tid >> 4;
    int m0 = blockIdx.y * 128, n0 = blockIdx.x * 128;
    float acc[8][8];
#pragma unroll
    for (int i = 0; i < 8; i++)
#pragma unroll
        for (int j = 0; j < 8; j++) acc[i][j] = 0.f;
    int lr = tid >> 2, lk4 = (tid & 3) * 4;
    for (int k0 = 0; k0 < K; k0 += 16) {
#pragma unroll
        for (int s = 0; s < 2; s++) {
            int rr = lr + s * 64;
            int gm = m0 + rr;
            float4 va = make_float4(0.f, 0.f, 0.f, 0.f);
            if (gm < M) va = *(const float4*)&A[(size_t)gm * K + k0 + lk4];
            As[lk4 + 0][rr] = va.x; As[lk4 + 1][rr] = va.y;
            As[lk4 + 2][rr] = va.z; As[lk4 + 3][rr] = va.w;
            float4 vb = *(const float4*)&B[(size_t)(n0 + rr) * K + k0 + lk4];
            Bs[lk4 + 0][rr] = vb.x; Bs[lk4 + 1][rr] = vb.y;
            Bs[lk4 + 2][rr] = vb.z; Bs[lk4 + 3][rr] = vb.w;
        }
        __syncthreads();
#pragma unroll
        for (int kk = 0; kk < 16; kk++) {
            float a[8], b[8];
            *(float4*)&a[0] = *(const float4*)&As[kk][ty * 8];
            *(float4*)&a[4] = *(const float4*)&As[kk][ty * 8 + 4];
            *(float4*)&b[0] = *(const float4*)&Bs[kk][tx * 8];
            *(float4*)&b[4] = *(const float4*)&Bs[kk][tx * 8 + 4];
#pragma unroll
            for (int i = 0; i < 8; i++)
#pragma unroll
                for (int j = 0; j < 8; j++) acc[i][j] += a[i] * b[j];
        }
        __syncthreads();
    }
#pragma unroll
    for (int i = 0; i < 8; i++) {
        int row = m0 + ty * 8 + i;
        if (row >= M) continue;
#pragma unroll
        for (int j = 0; j < 8; j++) {
            int col = n0 + tx * 8 + j;
            C[(size_t)row * N + col] = acc[i][j] + bias[col];
        }
    }
}

// ---------------------------------------------------------------------------
// LayerNorm + modulate, writes fp16
// ---------------------------------------------------------------------------
__global__ __launch_bounds__(256)
void ln_mod_kernel(const float* __restrict__ x, const float* __restrict__ mod,
                   int shift_ofs, int scale_ofs, __half* __restrict__ out) {
    int row = blockIdx.x;
    int b = row >> 10;
    const float* xr = x + (size_t)row * Cq;
    int tid = threadIdx.x;
    float v[4];
    float s = 0.f, s2 = 0.f;
#pragma unroll
    for (int t = 0; t < 4; t++) {
        float u = xr[tid + t * 256];
        v[t] = u; s += u; s2 += u * u;
    }
    __shared__ float sh[18];
#pragma unroll
    for (int o = 16; o > 0; o >>= 1) {
        s  += __shfl_down_sync(0xFFFFFFFFu, s, o);
        s2 += __shfl_down_sync(0xFFFFFFFFu, s2, o);
    }
    int wid = tid >> 5, lane = tid & 31;
    if (lane == 0) { sh[wid] = s; sh[wid + 8] = s2; }
    __syncthreads();
    if (tid == 0) {
        float a = 0.f, b2 = 0.f;
        for (int w = 0; w < 8; w++) { a += sh[w]; b2 += sh[w + 8]; }
        float mu = a * (1.f / 1024.f);
        float var = b2 * (1.f / 1024.f) - mu * mu;
        sh[16] = mu;
        sh[17] = rsqrtf(var + 1e-6f);
    }
    __syncthreads();
    float mu = sh[16], rs = sh[17];
    const float* mb = mod + (size_t)b * MODW;
    __half* orow = out + (size_t)row * Cq;
#pragma unroll
    for (int t = 0; t < 4; t++) {
        int cidx = tid + t * 256;
        float r = (v[t] - mu) * rs * (1.f + mb[scale_ofs + cidx]) + mb[shift_ofs + cidx];
        orow[cidx] = __float2half_rn(r);
    }
}

// ---------------------------------------------------------------------------
// Transpose V + sumV
// ---------------------------------------------------------------------------
__global__ __launch_bounds__(256)
void transpose_v(const __half* __restrict__ qkv, __half* __restrict__ vt,
                 float* __restrict__ sumv) {
    __shared__ __half t[32][34];
    int bh = blockIdx.z;
    int b = bh >> 4, h = bh & 15;
    int m0 = blockIdx.x * 32, d0 = blockIdx.y * 32;
    int tx = threadIdx.x & 31, ty = threadIdx.x >> 5;
#pragma unroll
    for (int i = 0; i < 32; i += 8)
        t[ty + i][tx] = qkv[(size_t)(b * 1024 + m0 + ty + i) * 3072 + 2048 + h * 64 + d0 + tx];
    __syncthreads();
#pragma unroll
    for (int i = 0; i < 32; i += 8)
        vt[(size_t)(bh * 64 + d0 + ty + i) * 1024 + m0 + tx] = t[tx][ty + i];
    if (ty == 0) {
        float s = 0.f;
#pragma unroll
        for (int m = 0; m < 32; m++) s += __half2float(t[m][tx]);
        atomicAdd(&sumv[bh * 64 + d0 + tx], s);
    }
}

// ---------------------------------------------------------------------------
// launch
// ---------------------------------------------------------------------------
extern "C" void kernel_launch(void* const* d_in, const int* in_sizes, int n_in,
                              void* d_out, int out_size) {
    (void)in_sizes; (void)n_in; (void)out_size;
    const float* x      = (const float*)d_in[0];
    const float* c      = (const float*)d_in[1];
    const void*  pmask  = d_in[2];
    const float* qkv_w  = (const float*)d_in[3];
    const float* qkv_b  = (const float*)d_in[4];
    const float* proj_w = (const float*)d_in[5];
    const float* proj_b = (const float*)d_in[6];
    const float* fc1_w  = (const float*)d_in[7];
    const float* fc1_b  = (const float*)d_in[8];
    const float* fc2_w  = (const float*)d_in[9];
    const float* fc2_b  = (const float*)d_in[10];
    const float* ada_w  = (const float*)d_in[11];
    const float* ada_b  = (const float*)d_in[12];
    float* out = (float*)d_out;

    void *p;
    cudaGetSymbolAddress(&p, g_silu_c);  float*  silu_c = (float*)p;
    cudaGetSymbolAddress(&p, g_mod);     float*  mod    = (float*)p;
    cudaGetSymbolAddress(&p, g_fmask);   float*  fmask  = (float*)p;
    cudaGetSymbolAddress(&p, g_lenq);    int*    lenq   = (int*)p;
    cudaGetSymbolAddress(&p, g_sumv);    float*  sumv   = (float*)p;
    cudaGetSymbolAddress(&p, g_x2);      float*  x2     = (float*)p;
    cudaGetSymbolAddress(&p, g_h16);     __half* h16    = (__half*)p;
    cudaGetSymbolAddress(&p, g_qkv16);   __half* qkv16  = (__half*)p;
    cudaGetSymbolAddress(&p, g_vt16);    __half* vt16   = (__half*)p;
    cudaGetSymbolAddress(&p, g_attn16);  __half* attn16 = (__half*)p;
    cudaGetSymbolAddress(&p, g_t16);     __half* t16    = (__half*)p;
    cudaGetSymbolAddress(&p, g_qkvw16);  __half* qkvw16 = (__half*)p;
    cudaGetSymbolAddress(&p, g_projw16); __half* projw16 = (__half*)p;
    cudaGetSymbolAddress(&p, g_fc1w16);  __half* fc1w16 = (__half*)p;
    cudaGetSymbolAddress(&p, g_fc2w16);  __half* fc2w16 = (__half*)p;

    const int SMEMG = STAGES * 2 * 128 * ROWB;   // 110592
    cudaFuncSetAttribute((const void*)gemm_h<0, 1, __half>, cudaFuncAttributeMaxDynamicSharedMemorySize, SMEMG);
    cudaFuncSetAttribute((const void*)gemm_h<1, 0, __half>, cudaFuncAttributeMaxDynamicSharedMemorySize, SMEMG);
    cudaFuncSetAttribute((const void*)gemm_pp<4>, cudaFuncAttributeMaxDynamicSharedMemorySize, SMEMG);
    cudaFuncSetAttribute((const void*)gemm_pp<6>, cudaFuncAttributeMaxDynamicSharedMemorySize, SMEMG);
    cudaFuncSetAttribute((const void*)fa_kernel, cudaFuncAttributeMaxDynamicSharedMemorySize, FA_SMEM);

    cudaMemsetAsync(lenq, 0, Bq * sizeof(int));

    cvt_all<<<(CV_TOT + 255) / 256, 256>>>(qkv_w, proj_w, fc1_w, fc2_w,
                                           qkvw16, projw16, fc1w16, fc2w16,
                                           c, pmask, silu_c, fmask, sumv, lenq);

    sgemm_ada<<<dim3(MODW / 128, 1), 256>>>(silu_c, ada_w, ada_b, mod, Bq, MODW, Cq);

    ln_mod_kernel<<<TOK, 256>>>(x, mod, 0, Cq, h16);

    // qkv = h @ qkv_w^T + b   [8192, 3072]  (Q/K padded-row tiles skipped)
    gemm_h<0, 1, __half><<<dim3(24, 64), 128, SMEMG>>>(
        h16, qkvw16, qkv_b, nullptr, nullptr, 0, qkv16, lenq, 1024, 1024, 3072, 1024);

    transpose_v<<<dim3(32, 2, 128), 256>>>(qkv16, vt16, sumv);

    fa_kernel<<<dim3(16, 128), 128, FA_SMEM>>>(qkv16, vt16, fmask, sumv, attn16);

    // x2 = x + gate_msa * (attn @ proj_w^T + b)  — persistent, K=1024 (LOGK=4)
    gemm_pp<4><<<PGRID, 256, SMEMG>>>(
        attn16, projw16, proj_b, x, mod, 2 * Cq, x2, 1024, 1024, 1024, 512);

    ln_mod_kernel<<<TOK, 256>>>(x2, mod, 3 * Cq, 4 * Cq, h16);

    // t = gelu(h @ fc1_w^T + b)   [8192, 4096]
    gemm_h<1, 0, __half><<<dim3(32, 64), 128, SMEMG>>>(
        h16, fc1w16, fc1_b, nullptr, nullptr, 0, t16, nullptr, 1024, 1024, 4096, 1024);

    // out = x2 + gate_mlp * (t @ fc2_w^T + b)  — persistent, K=4096 (LOGK=6)
    gemm_pp<6><<<PGRID, 256, SMEMG>>>(
        t16, fc2w16, fc2_b, x2, mod, 5 * Cq, out, 4096, 4096, 1024, 512);
}

// round 16
// speedup vs baseline: 1.0281x; 1.0281x over previous
#include <cuda_runtime.h>
#include <cuda_fp16.h>
#include <math.h>
#include <stdint.h>
#include <string.h>

// ---------------------------------------------------------------------------
// SiT block: B=8, N=1024, C=1024, H=16, HD=64, MLP=4096
// Round 16: R14 (best) + FA loads V via ldmatrix.trans from qkv16 directly.
// transpose_v and vt16 eliminated; sumv via small reduction kernel.
// ---------------------------------------------------------------------------

#define Bq 8
#define Nq 1024
#define Cq 1024
#define MLPq 4096
#define TOK (Bq * Nq)
#define MODW (6 * Cq)
#define STAGES 3
#define BKH 64
#define ROWB 144

// ----------------------------- scratch (static) ----------------------------
__device__ float  g_silu_c[Bq * Cq];
__device__ float  g_mod[Bq * MODW];
__device__ float  g_fmask[Bq * Nq];
__device__ int    g_lenq[Bq];
__device__ float  g_sumv[128 * 64];
__device__ float  g_x2[TOK * Cq];
__device__ __half g_h16[TOK * Cq];
__device__ __half g_qkv16[TOK * 3 * Cq];
__device__ __half g_attn16[TOK * Cq];
__device__ __half g_t16[TOK * MLPq];
__device__ __half g_qkvw16[3 * Cq * Cq];
__device__ __half g_projw16[Cq * Cq];
__device__ __half g_fc1w16[MLPq * Cq];
__device__ __half g_fc2w16[Cq * MLPq];

// ----------------------------- helpers -------------------------------------
__device__ __forceinline__ uint32_t smem_u32(const void* p) {
    uint32_t a;
    asm("{ .reg .u64 t; cvta.to.shared.u64 t, %1; cvt.u32.u64 %0, t; }" : "=r"(a) : "l"(p));
    return a;
}
__device__ __forceinline__ void cp16(uint32_t dst, const void* src) {
    asm volatile("cp.async.cg.shared.global [%0], [%1], 16;" :: "r"(dst), "l"(src));
}
__device__ __forceinline__ void cp_commit() {
    asm volatile("cp.async.commit_group;" ::: "memory");
}
template <int N>
__device__ __forceinline__ void cp_wait() {
    asm volatile("cp.async.wait_group %0;" :: "n"(N) : "memory");
}
__device__ __forceinline__ void ldsm4(uint32_t* r, uint32_t addr) {
    asm volatile("ldmatrix.sync.aligned.m8n8.x4.shared.b16 {%0,%1,%2,%3}, [%4];"
        : "=r"(r[0]), "=r"(r[1]), "=r"(r[2]), "=r"(r[3]) : "r"(addr));
}
__device__ __forceinline__ void ldsm4t(uint32_t* r, uint32_t addr) {
    asm volatile("ldmatrix.sync.aligned.m8n8.x4.trans.shared.b16 {%0,%1,%2,%3}, [%4];"
        : "=r"(r[0]), "=r"(r[1]), "=r"(r[2]), "=r"(r[3]) : "r"(addr));
}
__device__ __forceinline__ void mma16(float* c, const uint32_t* a, const uint32_t* b) {
    asm volatile("mma.sync.aligned.m16n8k16.row.col.f32.f16.f16.f32 "
        "{%0,%1,%2,%3}, {%4,%5,%6,%7}, {%8,%9}, {%0,%1,%2,%3};"
        : "+f"(c[0]), "+f"(c[1]), "+f"(c[2]), "+f"(c[3])
        : "r"(a[0]), "r"(a[1]), "r"(a[2]), "r"(a[3]), "r"(b[0]), "r"(b[1]));
}
__device__ __forceinline__ uint32_t packh2(float lo, float hi) {
    __half2 h = __floats2half2_rn(lo, hi);
    uint32_t u; memcpy(&u, &h, 4); return u;
}
__device__ __forceinline__ float gelu_tanh(float x) {
    float x3 = x * x * x;
    return 0.5f * x * (1.0f + tanhf(0.7978845608028654f * (x + 0.044715f * x3)));
}

// ---------------------------------------------------------------------------
// fp16 NT GEMM (R10 config): 128x128 CTA / 128 thr / warp 64x64 / BK=64 /
// 3 stages / double-buffered frags / 2 CTAs/SM.
// SKIP=1: skip tiles with n0 < 2048 whose 128 M-rows are all padded.
// EPI 0: +bias  1: gelu(+bias)  2: resid + gate*(+bias)
// ---------------------------------------------------------------------------
template <int EPI, int SKIP, typename OT>
__global__ __launch_bounds__(128, 2)
void gemm_h(const __half* __restrict__ A, const __half* __restrict__ B,
            const float* __restrict__ bias, const float* __restrict__ resid,
            const float* __restrict__ mod, int gate_ofs,
            OT* __restrict__ C, const int* __restrict__ lenq,
            int lda, int ldb, int ldc, int K) {
    constexpr int A_BY = 128 * ROWB;
    constexpr int STAGE_BY = 2 * A_BY;
    constexpr int M16 = 4, N8 = 8;

    extern __shared__ char dsm[];
    uint32_t sbase = smem_u32(dsm);
    int tid = threadIdx.x;
    int wid = tid >> 5, lane = tid & 31;
    int warpM = wid >> 1, warpN = wid & 1;
    int qid = lane >> 2, tq = lane & 3;

    int m0 = blockIdx.y * 128;
    int n0 = blockIdx.x * 128;

    if (SKIP) {
        if (n0 < 2048 && (m0 & 1023) >= lenq[m0 >> 10]) return;
    }

    float c[M16][N8][4];
#pragma unroll
    for (int i = 0; i < M16; i++)
#pragma unroll
        for (int j = 0; j < N8; j++)
#pragma unroll
            for (int q = 0; q < 4; q++) c[i][j][q] = 0.f;

    auto load_stage = [&](int st, int ks) {
        uint32_t ao = sbase + st * STAGE_BY;
        uint32_t bo = ao + A_BY;
        int k0 = ks * BKH;
#pragma unroll
        for (int j = 0; j < 8; j++) {
            int i = tid + j * 128;
            int r = i >> 3, ch = i & 7;
            cp16(ao + r * ROWB + ch * 16,
                 A + (size_t)(m0 + r) * lda + k0 + ch * 8);
        }
#pragma unroll
        for (int j = 0; j < 8; j++) {
            int i = tid + j * 128;
            int r = i >> 3, ch = i & 7;
            cp16(bo + r * ROWB + ch * 16,
                 B + (size_t)(n0 + r) * ldb + k0 + ch * 8);
        }
    };

    int kslabs = K / BKH;
    load_stage(0, 0); cp_commit();
    load_stage(1, 1); cp_commit();

    int aRow = lane & 15, aCol = (lane >> 4) * 16;
    int bRow = (lane & 7) + ((lane >> 4) << 3), bCol = ((lane >> 3) & 1) * 16;

    uint32_t af[2][M16][4];
    uint32_t bf[2][N8][2];

    auto load_frags = [&](uint32_t aBase, uint32_t bBase, int koff, int buf) {
#pragma unroll
        for (int m16 = 0; m16 < M16; m16++)
            ldsm4(af[buf][m16], aBase + (warpM * 64 + m16 * 16 + aRow) * ROWB + koff + aCol);
#pragma unroll
        for (int p = 0; p < N8 / 2; p++) {
            uint32_t r4[4];
            ldsm4(r4, bBase + (warpN * 64 + p * 16 + bRow) * ROWB + koff + bCol);
            bf[buf][2 * p][0] = r4[0]; bf[buf][2 * p][1] = r4[1];
            bf[buf][2 * p + 1][0] = r4[2]; bf[buf][2 * p + 1][1] = r4[3];
        }
    };

    for (int k = 0; k < kslabs; k++) {
        cp_wait<1>();
        __syncthreads();
        int kn = k + 2;
        if (kn < kslabs) load_stage(kn % STAGES, kn);
        cp_commit();

        uint32_t aBase = sbase + (k % STAGES) * STAGE_BY;
        uint32_t bBase = aBase + A_BY;

        load_frags(aBase, bBase, 0, 0);
#pragma unroll
        for (int ks = 0; ks < 4; ks++) {
            int cur = ks & 1;
            if (ks < 3) load_frags(aBase, bBase, (ks + 1) * 32, cur ^ 1);
#pragma unroll
            for (int m16 = 0; m16 < M16; m16++)
#pragma unroll
                for (int n8 = 0; n8 < N8; n8++)
                    mma16(c[m16][n8], af[cur][m16], bf[cur][n8]);
        }
    }

#pragma unroll
    for (int m16 = 0; m16 < M16; m16++) {
#pragma unroll
        for (int hh = 0; hh < 2; hh++) {
            int gr = m0 + warpM * 64 + m16 * 16 + hh * 8 + qid;
#pragma unroll
            for (int n8 = 0; n8 < N8; n8++) {
                int gcol = n0 + warpN * 64 + n8 * 8 + tq * 2;
                float v0 = c[m16][n8][hh * 2 + 0];
                float v1 = c[m16][n8][hh * 2 + 1];
                {
                    float2 b2 = *(const float2*)&bias[gcol];
                    v0 += b2.x; v1 += b2.y;
                }
                if (EPI == 1) { v0 = gelu_tanh(v0); v1 = gelu_tanh(v1); }
                if (EPI == 2) {
                    float2 g2 = *(const float2*)&mod[(size_t)(gr >> 10) * MODW + gate_ofs + gcol];
                    float2 r2 = *(const float2*)&resid[(size_t)gr * ldc + gcol];
                    v0 = r2.x + g2.x * v0;
                    v1 = r2.y + g2.y * v1;
                }
                OT* dst = &C[(size_t)gr * ldc + gcol];
                if (sizeof(OT) == 2) {
                    __half2 hv = __floats2half2_rn(v0, v1);
                    *(__half2*)dst = hv;
                } else {
                    *(float2*)dst = make_float2(v0, v1);
                }
            }
        }
    }
}

// ---------------------------------------------------------------------------
// Fused flash attention: 128-thr CTA / 64 q rows / 2-stage KV ring / 2 CTAs/SM.
// V loaded ROW-MAJOR straight from qkv16; V^T fragments via ldmatrix.trans.
// Dead q-tiles short-circuit to sumv fallback.
// ---------------------------------------------------------------------------
#define FA_QOFF 0
#define FA_FOFF 9216
#define FA_KOFF 13312
#define FA_KST  18432          // 128 rows * 144 B
#define FA_VOFF 50176
#define FA_VST  18432          // 128 rows * 144 B (row-major V)
#define FA_SMEM 87040

__global__ __launch_bounds__(128, 2)
void fa_kernel(const __half* __restrict__ qkv,
               const float* __restrict__ fmask, const float* __restrict__ sumv,
               __half* __restrict__ attn) {
    extern __shared__ char dsm[];
    __shared__ float sred[4];
    __shared__ int s_nt;
    uint32_t sb = smem_u32(dsm);
    const float* smF = (const float*)(dsm + FA_FOFF);
    int tid = threadIdx.x, wid = tid >> 5, lane = tid & 31;
    int qid = lane >> 2, tq = lane & 3;
    int by = blockIdx.y;
    int b = by >> 4, h = by & 15;
    int q0 = blockIdx.x * 64;

    if (fmask[b * 1024 + q0] == 0.f) {
        const float* sv = sumv + by * 64;
        int gr0 = q0 + wid * 16 + qid;
        __half* o0 = attn + ((size_t)(b * 1024) + gr0) * 1024 + h * 64;
        __half* o1 = o0 + (size_t)8 * 1024;
#pragma unroll
        for (int t = 0; t < 8; t++) {
            float2 s2 = *(const float2*)&sv[8 * t + 2 * tq];
            __half2 hv = __floats2half2_rn(s2.x * (1.f / 1024.f), s2.y * (1.f / 1024.f));
            *(__half2*)(o0 + 8 * t + 2 * tq) = hv;
            *(__half2*)(o1 + 8 * t + 2 * tq) = hv;
        }
        return;
    }

    const __half* Qg = qkv + ((size_t)(b * 1024 + q0)) * 3072 + h * 64;
    const __half* Kg = qkv + ((size_t)(b * 1024)) * 3072 + 1024 + h * 64;
    const __half* Vg = qkv + ((size_t)(b * 1024)) * 3072 + 2048 + h * 64;

    auto loadKV = [&](int st, int kt) {
#pragma unroll
        for (int j = 0; j < 8; j++) {               // K: 128 rows x 8 chunks
            int i = tid + j * 128;
            int r = i >> 3, ch = i & 7;
            cp16(sb + FA_KOFF + st * FA_KST + r * 144 + ch * 16,
                 Kg + (size_t)(kt * 128 + r) * 3072 + ch * 8);
        }
#pragma unroll
        for (int j = 0; j < 8; j++) {               // V row-major: 128 rows x 8 chunks
            int i = tid + j * 128;
            int r = i >> 3, ch = i & 7;
            cp16(sb + FA_VOFF + st * FA_VST + r * 144 + ch * 16,
                 Vg + (size_t)(kt * 128 + r) * 3072 + ch * 8);
        }
    };

#pragma unroll
    for (int j = 0; j < 4; j++) {
        int i = tid + j * 128;
        int r = i >> 3, ch = i & 7;
        cp16(sb + FA_QOFF + r * 144 + ch * 16, Qg + (size_t)r * 3072 + ch * 8);
    }
    cp16(sb + FA_FOFF + tid * 32, fmask + b * 1024 + tid * 8);
    cp16(sb + FA_FOFF + tid * 32 + 16, fmask + b * 1024 + tid * 8 + 4);
    loadKV(0, 0);
    cp_commit();

    int aRow = lane & 15, aCol = (lane >> 4) * 16;
    int bRow = (lane & 7) + ((lane >> 4) << 3), bCol = ((lane >> 3) & 1) * 16;
    int vRow = (lane & 7) + (((lane >> 3) & 1) << 3), vCol = (lane >> 4) * 16;
    int r0 = wid * 16;

    cp_wait<0>();
    __syncthreads();

    {
        float cnt = 0.f;
        float4 m4a = *(const float4*)(smF + tid * 8);
        float4 m4b = *(const float4*)(smF + tid * 8 + 4);
        cnt = (m4a.x != 0.f) + (m4a.y != 0.f) + (m4a.z != 0.f) + (m4a.w != 0.f)
            + (m4b.x != 0.f) + (m4b.y != 0.f) + (m4b.z != 0.f) + (m4b.w != 0.f);
#pragma unroll
        for (int o = 16; o > 0; o >>= 1) cnt += __shfl_down_sync(0xFFFFFFFFu, cnt, o);
        if (lane == 0) sred[wid] = cnt;
        __syncthreads();
        if (tid == 0) {
            float tot = sred[0] + sred[1] + sred[2] + sred[3];
            s_nt = ((int)(tot + 0.5f) + 127) >> 7;
        }
        __syncthreads();
    }
    int ntiles = s_nt;

    uint32_t qa[4][4];
#pragma unroll
    for (int ks = 0; ks < 4; ks++)
        ldsm4(qa[ks], sb + FA_QOFF + (r0 + aRow) * 144 + ks * 32 + aCol);

    float O[8][4];
#pragma unroll
    for (int t = 0; t < 8; t++)
#pragma unroll
        for (int q = 0; q < 4; q++) O[t][q] = 0.f;
    float m0 = -3.0e38f, m1 = -3.0e38f, l0 = 0.f, l1 = 0.f;

    for (int kt = 0; kt < ntiles; kt++) {
        if (kt > 0) { cp_wait<0>(); __syncthreads(); }
        if (kt + 1 < ntiles) loadKV((kt + 1) & 1, kt + 1);
        cp_commit();

        uint32_t Ks = sb + FA_KOFF + (kt & 1) * FA_KST;
        uint32_t Vs = sb + FA_VOFF + (kt & 1) * FA_VST;

        // S = Q K^T
        float sc[16][4];
#pragma unroll
        for (int j = 0; j < 16; j++)
#pragma unroll
            for (int q = 0; q < 4; q++) sc[j][q] = 0.f;
#pragma unroll
        for (int ks = 0; ks < 4; ks++) {
            uint32_t kb[16][2];
#pragma unroll
            for (int p = 0; p < 8; p++) {
                uint32_t r4[4];
                ldsm4(r4, Ks + (16 * p + bRow) * 144 + ks * 32 + bCol);
                kb[2 * p][0] = r4[0]; kb[2 * p][1] = r4[1];
                kb[2 * p + 1][0] = r4[2]; kb[2 * p + 1][1] = r4[3];
            }
#pragma unroll
            for (int j = 0; j < 16; j++) mma16(sc[j], qa[ks], kb[j]);
        }

        bool mr0 = smF[q0 + r0 + qid] != 0.f;
        bool mr1 = smF[q0 + r0 + qid + 8] != 0.f;
#pragma unroll
        for (int j = 0; j < 16; j++) {
            int kvc = kt * 128 + 8 * j + 2 * tq;
            bool mk0 = smF[kvc] != 0.f;
            bool mk1 = smF[kvc + 1] != 0.f;
            sc[j][0] = (mr0 && mk0) ? sc[j][0] * 0.125f : -1e9f;
            sc[j][1] = (mr0 && mk1) ? sc[j][1] * 0.125f : -1e9f;
            sc[j][2] = (mr1 && mk0) ? sc[j][2] * 0.125f : -1e9f;
            sc[j][3] = (mr1 && mk1) ? sc[j][3] * 0.125f : -1e9f;
        }

        float mx0 = -3.0e38f, mx1 = -3.0e38f;
#pragma unroll
        for (int j = 0; j < 16; j++) {
            mx0 = fmaxf(mx0, fmaxf(sc[j][0], sc[j][1]));
            mx1 = fmaxf(mx1, fmaxf(sc[j][2], sc[j][3]));
        }
        mx0 = fmaxf(mx0, __shfl_xor_sync(0xFFFFFFFFu, mx0, 1));
        mx0 = fmaxf(mx0, __shfl_xor_sync(0xFFFFFFFFu, mx0, 2));
        mx1 = fmaxf(mx1, __shfl_xor_sync(0xFFFFFFFFu, mx1, 1));
        mx1 = fmaxf(mx1, __shfl_xor_sync(0xFFFFFFFFu, mx1, 2));
        float nm0 = fmaxf(m0, mx0), nm1 = fmaxf(m1, mx1);
        float cr0 = __expf(m0 - nm0), cr1 = __expf(m1 - nm1);
        m0 = nm0; m1 = nm1;
        float rs0 = 0.f, rs1 = 0.f;
#pragma unroll
        for (int j = 0; j < 16; j++) {
            sc[j][0] = __expf(sc[j][0] - m0);
            sc[j][1] = __expf(sc[j][1] - m0);
            sc[j][2] = __expf(sc[j][2] - m1);
            sc[j][3] = __expf(sc[j][3] - m1);
            rs0 += sc[j][0] + sc[j][1];
            rs1 += sc[j][2] + sc[j][3];
        }
        rs0 += __shfl_xor_sync(0xFFFFFFFFu, rs0, 1);
        rs0 += __shfl_xor_sync(0xFFFFFFFFu, rs0, 2);
        rs1 += __shfl_xor_sync(0xFFFFFFFFu, rs1, 1);
        rs1 += __shfl_xor_sync(0xFFFFFFFFu, rs1, 2);
        l0 = l0 * cr0 + rs0;
        l1 = l1 * cr1 + rs1;
#pragma unroll
        for (int t = 0; t < 8; t++) {
            O[t][0] *= cr0; O[t][1] *= cr0;
            O[t][2] *= cr1; O[t][3] *= cr1;
        }

        uint32_t pa[8][4];
#pragma unroll
        for (int k = 0; k < 8; k++) {
            pa[k][0] = packh2(sc[2 * k][0], sc[2 * k][1]);
            pa[k][1] = packh2(sc[2 * k][2], sc[2 * k][3]);
            pa[k][2] = packh2(sc[2 * k + 1][0], sc[2 * k + 1][1]);
            pa[k][3] = packh2(sc[2 * k + 1][2], sc[2 * k + 1][3]);
        }

        // O += P V : V^T fragments via ldmatrix.trans of row-major V tile.
        // k-chunk = 16 kv rows; per p: 16 d columns (32 bytes).
#pragma unroll
        for (int k = 0; k < 8; k++) {
            uint32_t vb[8][2];
#pragma unroll
            for (int p = 0; p < 4; p++) {
                uint32_t r4[4];
                ldsm4t(r4, Vs + (16 * k + vRow) * 144 + p * 32 + vCol);
                vb[2 * p][0] = r4[0]; vb[2 * p][1] = r4[1];
                vb[2 * p + 1][0] = r4[2]; vb[2 * p + 1][1] = r4[3];
            }
#pragma unroll
            for (int t = 0; t < 8; t++) mma16(O[t], pa[k], vb[t]);
        }
    }

    bool mr0 = smF[q0 + r0 + qid] != 0.f;
    bool mr1 = smF[q0 + r0 + qid + 8] != 0.f;
    float li0 = 1.f / l0, li1 = 1.f / l1;
    int gr0 = q0 + r0 + qid;
    __half* o0 = attn + ((size_t)(b * 1024) + gr0) * 1024 + h * 64;
    __half* o1 = o0 + (size_t)8 * 1024;
    const float* sv = sumv + by * 64;
#pragma unroll
    for (int t = 0; t < 8; t++) {
        float2 s2 = *(const float2*)&sv[8 * t + 2 * tq];
        float u0 = mr0 ? O[t][0] * li0 : s2.x * (1.f / 1024.f);
        float u1 = mr0 ? O[t][1] * li0 : s2.y * (1.f / 1024.f);
        float u2 = mr1 ? O[t][2] * li1 : s2.x * (1.f / 1024.f);
        float u3 = mr1 ? O[t][3] * li1 : s2.y * (1.f / 1024.f);
        *(__half2*)(o0 + 8 * t + 2 * tq) = __floats2half2_rn(u0, u1);
        *(__half2*)(o1 + 8 * t + 2 * tq) = __floats2half2_rn(u2, u3);
    }
}

// ---------------------------------------------------------------------------
// sumV reduction: one CTA per (b,h); 256 thr = 4 m-chunks x 64 d.
// ---------------------------------------------------------------------------
__global__ __launch_bounds__(256)
void sumv_kernel(const __half* __restrict__ qkv, float* __restrict__ sumv) {
    __shared__ float sh[256];
    int by = blockIdx.x;
    int b = by >> 4, h = by & 15;
    int tid = threadIdx.x;
    int d = tid & 63, mc = tid >> 6;
    const __half* Vg = qkv + (size_t)b * 1024 * 3072 + 2048 + h * 64 + d;
    float s = 0.f;
    for (int m = mc * 256; m < mc * 256 + 256; m++)
        s += __half2float(Vg[(size_t)m * 3072]);
    sh[tid] = s;
    __syncthreads();
    if (tid < 64)
        sumv[by * 64 + tid] = sh[tid] + sh[tid + 64] + sh[tid + 128] + sh[tid + 192];
}

// ---------------------------------------------------------------------------
// Merged weight conversion + prep + length accumulation
// ---------------------------------------------------------------------------
#define CV_Q 1572864
#define CV_P (CV_Q + 524288)
#define CV_F1 (CV_P + 2097152)
#define CV_TOT (CV_F1 + 2097152)

__global__ void cvt_all(const float* __restrict__ qkv_w, const float* __restrict__ proj_w,
                        const float* __restrict__ fc1_w, const float* __restrict__ fc2_w,
                        __half* __restrict__ o_qkv, __half* __restrict__ o_proj,
                        __half* __restrict__ o_fc1, __half* __restrict__ o_fc2,
                        const float* __restrict__ c, const void* __restrict__ mask,
                        float* __restrict__ silu_c, float* __restrict__ fmask,
                        int* __restrict__ lenq) {
    int i = blockIdx.x * blockDim.x + threadIdx.x;
    if (i < Bq * Cq) {
        float v = c[i];
        silu_c[i] = v / (1.0f + expf(-v));
        unsigned w0 = *(const unsigned*)mask;
        float mv;
        if (w0 == 0x3F800000u)        mv = ((const float*)mask)[i];
        else if (w0 == 0x01010101u)   mv = ((const unsigned char*)mask)[i] ? 1.f : 0.f;
        else                          mv = ((const int*)mask)[i] ? 1.f : 0.f;
        bool on = (mv != 0.f);
        fmask[i] = on ? 1.f : 0.f;
        if (on) atomicAdd(&lenq[i >> 10], 1);
    }
    if (i >= CV_TOT) return;
    const float* s; __half* d; int off;
    if (i < CV_Q)        { s = qkv_w;  d = o_qkv;  off = i; }
    else if (i < CV_P)   { s = proj_w; d = o_proj; off = i - CV_Q; }
    else if (i < CV_F1)  { s = fc1_w;  d = o_fc1;  off = i - CV_P; }
    else                 { s = fc2_w;  d = o_fc2;  off = i - CV_F1; }
    float2 v = *(const float2*)&s[off * 2];
    *(__half2*)&d[off * 2] = __floats2half2_rn(v.x, v.y);
}

// ---------------------------------------------------------------------------
// fp32 SGEMM for the tiny ada GEMM (M=8)
// ---------------------------------------------------------------------------
__global__ __launch_bounds__(256)
void sgemm_ada(const float* __restrict__ A, const float* __restrict__ B,
               const float* __restrict__ bias, float* __restrict__ C,
               int M, int N, int K) {
    __shared__ float As[16][128];
    __shared__ float Bs[16][128];
    int tid = threadIdx.x;
    int tx = tid & 15, ty = tid >> 4;
    int m0 = blockIdx.y * 128, n0 = blockIdx.x * 128;
    float acc[8][8];
#pragma unroll
    for (int i = 0; i < 8; i++)
#pragma unroll
        for (int j = 0; j < 8; j++) acc[i][j] = 0.f;
    int lr = tid >> 2, lk4 = (tid & 3) * 4;
    for (int k0 = 0; k0 < K; k0 += 16) {
#pragma unroll
        for (int s = 0; s < 2; s++) {
            int rr = lr + s * 64;
            int gm = m0 + rr;
            float4 va = make_float4(0.f, 0.f, 0.f, 0.f);
            if (gm < M) va = *(const float4*)&A[(size_t)gm * K + k0 + lk4];
            As[lk4 + 0][rr] = va.x; As[lk4 + 1][rr] = va.y;
            As[lk4 + 2][rr] = va.z; As[lk4 + 3][rr] = va.w;
            float4 vb = *(const float4*)&B[(size_t)(n0 + rr) * K + k0 + lk4];
            Bs[lk4 + 0][rr] = vb.x; Bs[lk4 + 1][rr] = vb.y;
            Bs[lk4 + 2][rr] = vb.z; Bs[lk4 + 3][rr] = vb.w;
        }
        __syncthreads();
#pragma unroll
        for (int kk = 0; kk < 16; kk++) {
            float a[8], b[8];
            *(float4*)&a[0] = *(const float4*)&As[kk][ty * 8];
            *(float4*)&a[4] = *(const float4*)&As[kk][ty * 8 + 4];
            *(float4*)&b[0] = *(const float4*)&Bs[kk][tx * 8];
            *(float4*)&b[4] = *(const float4*)&Bs[kk][tx * 8 + 4];
#pragma unroll
            for (int i = 0; i < 8; i++)
#pragma unroll
                for (int j = 0; j < 8; j++) acc[i][j] += a[i] * b[j];
        }
        __syncthreads();
    }
#pragma unroll
    for (int i = 0; i < 8; i++) {
        int row = m0 + ty * 8 + i;
        if (row >= M) continue;
#pragma unroll
        for (int j = 0; j < 8; j++) {
            int col = n0 + tx * 8 + j;
            C[(size_t)row * N + col] = acc[i][j] + bias[col];
        }
    }
}

// ---------------------------------------------------------------------------
// LayerNorm + modulate, writes fp16
// ---------------------------------------------------------------------------
__global__ __launch_bounds__(256)
void ln_mod_kernel(const float* __restrict__ x, const float* __restrict__ mod,
                   int shift_ofs, int scale_ofs, __half* __restrict__ out) {
    int row = blockIdx.x;
    int b = row >> 10;
    const float* xr = x + (size_t)row * Cq;
    int tid = threadIdx.x;
    float v[4];
    float s = 0.f, s2 = 0.f;
#pragma unroll
    for (int t = 0; t < 4; t++) {
        float u = xr[tid + t * 256];
        v[t] = u; s += u; s2 += u * u;
    }
    __shared__ float sh[18];
#pragma unroll
    for (int o = 16; o > 0; o >>= 1) {
        s  += __shfl_down_sync(0xFFFFFFFFu, s, o);
        s2 += __shfl_down_sync(0xFFFFFFFFu, s2, o);
    }
    int wid = tid >> 5, lane = tid & 31;
    if (lane == 0) { sh[wid] = s; sh[wid + 8] = s2; }
    __syncthreads();
    if (tid == 0) {
        float a = 0.f, b2 = 0.f;
        for (int w = 0; w < 8; w++) { a += sh[w]; b2 += sh[w + 8]; }
        float mu = a * (1.f / 1024.f);
        float var = b2 * (1.f / 1024.f) - mu * mu;
        sh[16] = mu;
        sh[17] = rsqrtf(var + 1e-6f);
    }
    __syncthreads();
    float mu = sh[16], rs = sh[17];
    const float* mb = mod + (size_t)b * MODW;
    __half* orow = out + (size_t)row * Cq;
#pragma unroll
    for (int t = 0; t < 4; t++) {
        int cidx = tid + t * 256;
        float r = (v[t] - mu) * rs * (1.f + mb[scale_ofs + cidx]) + mb[shift_ofs + cidx];
        orow[cidx] = __float2half_rn(r);
    }
}

// ---------------------------------------------------------------------------
// launch
// ---------------------------------------------------------------------------
extern "C" void kernel_launch(void* const* d_in, const int* in_sizes, int n_in,
                              void* d_out, int out_size) {
    (void)in_sizes; (void)n_in; (void)out_size;
    const float* x      = (const float*)d_in[0];
    const float* c      = (const float*)d_in[1];
    const void*  pmask  = d_in[2];
    const float* qkv_w  = (const float*)d_in[3];
    const float* qkv_b  = (const float*)d_in[4];
    const float* proj_w = (const float*)d_in[5];
    const float* proj_b = (const float*)d_in[6];
    const float* fc1_w  = (const float*)d_in[7];
    const float* fc1_b  = (const float*)d_in[8];
    const float* fc2_w  = (const float*)d_in[9];
    const float* fc2_b  = (const float*)d_in[10];
    const float* ada_w  = (const float*)d_in[11];
    const float* ada_b  = (const float*)d_in[12];
    float* out = (float*)d_out;

    void *p;
    cudaGetSymbolAddress(&p, g_silu_c);  float*  silu_c = (float*)p;
    cudaGetSymbolAddress(&p, g_mod);     float*  mod    = (float*)p;
    cudaGetSymbolAddress(&p, g_fmask);   float*  fmask  = (float*)p;
    cudaGetSymbolAddress(&p, g_lenq);    int*    lenq   = (int*)p;
    cudaGetSymbolAddress(&p, g_sumv);    float*  sumv   = (float*)p;
    cudaGetSymbolAddress(&p, g_x2);      float*  x2     = (float*)p;
    cudaGetSymbolAddress(&p, g_h16);     __half* h16    = (__half*)p;
    cudaGetSymbolAddress(&p, g_qkv16);   __half* qkv16  = (__half*)p;
    cudaGetSymbolAddress(&p, g_attn16);  __half* attn16 = (__half*)p;
    cudaGetSymbolAddress(&p, g_t16);     __half* t16    = (__half*)p;
    cudaGetSymbolAddress(&p, g_qkvw16);  __half* qkvw16 = (__half*)p;
    cudaGetSymbolAddress(&p, g_projw16); __half* projw16 = (__half*)p;
    cudaGetSymbolAddress(&p, g_fc1w16);  __half* fc1w16 = (__half*)p;
    cudaGetSymbolAddress(&p, g_fc2w16);  __half* fc2w16 = (__half*)p;

    const int SMEMG = STAGES * 2 * 128 * ROWB;   // 110592
    cudaFuncSetAttribute((const void*)gemm_h<0, 1, __half>, cudaFuncAttributeMaxDynamicSharedMemorySize, SMEMG);
    cudaFuncSetAttribute((const void*)gemm_h<1, 0, __half>, cudaFuncAttributeMaxDynamicSharedMemorySize, SMEMG);
    cudaFuncSetAttribute((const void*)gemm_h<2, 0, float>,  cudaFuncAttributeMaxDynamicSharedMemorySize, SMEMG);
    cudaFuncSetAttribute((const void*)fa_kernel, cudaFuncAttributeMaxDynamicSharedMemorySize, FA_SMEM);

    cudaMemsetAsync(lenq, 0, Bq * sizeof(int));

    cvt_all<<<(CV_TOT + 255) / 256, 256>>>(qkv_w, proj_w, fc1_w, fc2_w,
                                           qkvw16, projw16, fc1w16, fc2w16,
                                           c, pmask, silu_c, fmask, lenq);

    sgemm_ada<<<dim3(MODW / 128, 1), 256>>>(silu_c, ada_w, ada_b, mod, Bq, MODW, Cq);

    ln_mod_kernel<<<TOK, 256>>>(x, mod, 0, Cq, h16);

    // qkv = h @ qkv_w^T + b   [8192, 3072]  (Q/K padded-row tiles skipped)
    gemm_h<0, 1, __half><<<dim3(24, 64), 128, SMEMG>>>(
        h16, qkvw16, qkv_b, nullptr, nullptr, 0, qkv16, lenq, 1024, 1024, 3072, 1024);

    // sumV (replaces transpose_v)
    sumv_kernel<<<128, 256>>>(qkv16, sumv);

    // fused flash attention (V via ldmatrix.trans, no transpose buffer)
    fa_kernel<<<dim3(16, 128), 128, FA_SMEM>>>(qkv16, fmask, sumv, attn16);

    // x2 = x + gate_msa * (attn @ proj_w^T + b)
    gemm_h<2, 0, float><<<dim3(8, 64), 128, SMEMG>>>(
        attn16, projw16, proj_b, x, mod, 2 * Cq, x2, nullptr, 1024, 1024, 1024, 1024);

    ln_mod_kernel<<<TOK, 256>>>(x2, mod, 3 * Cq, 4 * Cq, h16);

    // t = gelu(h @ fc1_w^T + b)   [8192, 4096]
    gemm_h<1, 0, __half><<<dim3(32, 64), 128, SMEMG>>>(
        h16, fc1w16, fc1_b, nullptr, nullptr, 0, t16, nullptr, 1024, 1024, 4096, 1024);

    // out = x2 + gate_mlp * (t @ fc2_w^T + b)
    gemm_h<2, 0, float><<<dim3(8, 64), 128, SMEMG>>>(
        t16, fc2w16, fc2_b, x2, mod, 5 * Cq, out, nullptr, 4096, 4096, 1024, 4096);
}

// round 17
// speedup vs baseline: 1.0281x; 1.0001x over previous
#include <cuda_runtime.h>
#include <cuda_fp16.h>
#include <math.h>
#include <stdint.h>
#include <string.h>

// ---------------------------------------------------------------------------
// SiT block: B=8, N=1024, C=1024, H=16, HD=64, MLP=4096
// Round 17: R16 + FA softmax via ex2.approx.f16x2 (halves MUFU work; exp
// output doubles as the PV fp16 fragment).
// ---------------------------------------------------------------------------

#define Bq 8
#define Nq 1024
#define Cq 1024
#define MLPq 4096
#define TOK (Bq * Nq)
#define MODW (6 * Cq)
#define STAGES 3
#define BKH 64
#define ROWB 144

// ----------------------------- scratch (static) ----------------------------
__device__ float  g_silu_c[Bq * Cq];
__device__ float  g_mod[Bq * MODW];
__device__ float  g_fmask[Bq * Nq];
__device__ int    g_lenq[Bq];
__device__ float  g_sumv[128 * 64];
__device__ float  g_x2[TOK * Cq];
__device__ __half g_h16[TOK * Cq];
__device__ __half g_qkv16[TOK * 3 * Cq];
__device__ __half g_attn16[TOK * Cq];
__device__ __half g_t16[TOK * MLPq];
__device__ __half g_qkvw16[3 * Cq * Cq];
__device__ __half g_projw16[Cq * Cq];
__device__ __half g_fc1w16[MLPq * Cq];
__device__ __half g_fc2w16[Cq * MLPq];

// ----------------------------- helpers -------------------------------------
__device__ __forceinline__ uint32_t smem_u32(const void* p) {
    uint32_t a;
    asm("{ .reg .u64 t; cvta.to.shared.u64 t, %1; cvt.u32.u64 %0, t; }" : "=r"(a) : "l"(p));
    return a;
}
__device__ __forceinline__ void cp16(uint32_t dst, const void* src) {
    asm volatile("cp.async.cg.shared.global [%0], [%1], 16;" :: "r"(dst), "l"(src));
}
__device__ __forceinline__ void cp_commit() {
    asm volatile("cp.async.commit_group;" ::: "memory");
}
template <int N>
__device__ __forceinline__ void cp_wait() {
    asm volatile("cp.async.wait_group %0;" :: "n"(N) : "memory");
}
__device__ __forceinline__ void ldsm4(uint32_t* r, uint32_t addr) {
    asm volatile("ldmatrix.sync.aligned.m8n8.x4.shared.b16 {%0,%1,%2,%3}, [%4];"
        : "=r"(r[0]), "=r"(r[1]), "=r"(r[2]), "=r"(r[3]) : "r"(addr));
}
__device__ __forceinline__ void ldsm4t(uint32_t* r, uint32_t addr) {
    asm volatile("ldmatrix.sync.aligned.m8n8.x4.trans.shared.b16 {%0,%1,%2,%3}, [%4];"
        : "=r"(r[0]), "=r"(r[1]), "=r"(r[2]), "=r"(r[3]) : "r"(addr));
}
__device__ __forceinline__ void mma16(float* c, const uint32_t* a, const uint32_t* b) {
    asm volatile("mma.sync.aligned.m16n8k16.row.col.f32.f16.f16.f32 "
        "{%0,%1,%2,%3}, {%4,%5,%6,%7}, {%8,%9}, {%0,%1,%2,%3};"
        : "+f"(c[0]), "+f"(c[1]), "+f"(c[2]), "+f"(c[3])
        : "r"(a[0]), "r"(a[1]), "r"(a[2]), "r"(a[3]), "r"(b[0]), "r"(b[1]));
}
__device__ __forceinline__ uint32_t packh2(float lo, float hi) {
    __half2 h = __floats2half2_rn(lo, hi);
    uint32_t u; memcpy(&u, &h, 4); return u;
}
__device__ __forceinline__ uint32_t h2ex2(uint32_t u) {
    uint32_t r;
    asm("ex2.approx.f16x2 %0, %1;" : "=r"(r) : "r"(u));
    return r;
}
__device__ __forceinline__ float2 h2f2(uint32_t u) {
    __half2 h; memcpy(&h, &u, 4);
    return __half22float2(h);
}
__device__ __forceinline__ float gelu_tanh(float x) {
    float x3 = x * x * x;
    return 0.5f * x * (1.0f + tanhf(0.7978845608028654f * (x + 0.044715f * x3)));
}

// ---------------------------------------------------------------------------
// fp16 NT GEMM (R10 config): 128x128 CTA / 128 thr / warp 64x64 / BK=64 /
// 3 stages / double-buffered frags / 2 CTAs/SM.
// SKIP=1: skip tiles with n0 < 2048 whose 128 M-rows are all padded.
// EPI 0: +bias  1: gelu(+bias)  2: resid + gate*(+bias)
// ---------------------------------------------------------------------------
template <int EPI, int SKIP, typename OT>
__global__ __launch_bounds__(128, 2)
void gemm_h(const __half* __restrict__ A, const __half* __restrict__ B,
            const float* __restrict__ bias, const float* __restrict__ resid,
            const float* __restrict__ mod, int gate_ofs,
            OT* __restrict__ C, const int* __restrict__ lenq,
            int lda, int ldb, int ldc, int K) {
    constexpr int A_BY = 128 * ROWB;
    constexpr int STAGE_BY = 2 * A_BY;
    constexpr int M16 = 4, N8 = 8;

    extern __shared__ char dsm[];
    uint32_t sbase = smem_u32(dsm);
    int tid = threadIdx.x;
    int wid = tid >> 5, lane = tid & 31;
    int warpM = wid >> 1, warpN = wid & 1;
    int qid = lane >> 2, tq = lane & 3;

    int m0 = blockIdx.y * 128;
    int n0 = blockIdx.x * 128;

    if (SKIP) {
        if (n0 < 2048 && (m0 & 1023) >= lenq[m0 >> 10]) return;
    }

    float c[M16][N8][4];
#pragma unroll
    for (int i = 0; i < M16; i++)
#pragma unroll
        for (int j = 0; j < N8; j++)
#pragma unroll
            for (int q = 0; q < 4; q++) c[i][j][q] = 0.f;

    auto load_stage = [&](int st, int ks) {
        uint32_t ao = sbase + st * STAGE_BY;
        uint32_t bo = ao + A_BY;
        int k0 = ks * BKH;
#pragma unroll
        for (int j = 0; j < 8; j++) {
            int i = tid + j * 128;
            int r = i >> 3, ch = i & 7;
            cp16(ao + r * ROWB + ch * 16,
                 A + (size_t)(m0 + r) * lda + k0 + ch * 8);
        }
#pragma unroll
        for (int j = 0; j < 8; j++) {
            int i = tid + j * 128;
            int r = i >> 3, ch = i & 7;
            cp16(bo + r * ROWB + ch * 16,
                 B + (size_t)(n0 + r) * ldb + k0 + ch * 8);
        }
    };

    int kslabs = K / BKH;
    load_stage(0, 0); cp_commit();
    load_stage(1, 1); cp_commit();

    int aRow = lane & 15, aCol = (lane >> 4) * 16;
    int bRow = (lane & 7) + ((lane >> 4) << 3), bCol = ((lane >> 3) & 1) * 16;

    uint32_t af[2][M16][4];
    uint32_t bf[2][N8][2];

    auto load_frags = [&](uint32_t aBase, uint32_t bBase, int koff, int buf) {
#pragma unroll
        for (int m16 = 0; m16 < M16; m16++)
            ldsm4(af[buf][m16], aBase + (warpM * 64 + m16 * 16 + aRow) * ROWB + koff + aCol);
#pragma unroll
        for (int p = 0; p < N8 / 2; p++) {
            uint32_t r4[4];
            ldsm4(r4, bBase + (warpN * 64 + p * 16 + bRow) * ROWB + koff + bCol);
            bf[buf][2 * p][0] = r4[0]; bf[buf][2 * p][1] = r4[1];
            bf[buf][2 * p + 1][0] = r4[2]; bf[buf][2 * p + 1][1] = r4[3];
        }
    };

    for (int k = 0; k < kslabs; k++) {
        cp_wait<1>();
        __syncthreads();
        int kn = k + 2;
        if (kn < kslabs) load_stage(kn % STAGES, kn);
        cp_commit();

        uint32_t aBase = sbase + (k % STAGES) * STAGE_BY;
        uint32_t bBase = aBase + A_BY;

        load_frags(aBase, bBase, 0, 0);
#pragma unroll
        for (int ks = 0; ks < 4; ks++) {
            int cur = ks & 1;
            if (ks < 3) load_frags(aBase, bBase, (ks + 1) * 32, cur ^ 1);
#pragma unroll
            for (int m16 = 0; m16 < M16; m16++)
#pragma unroll
                for (int n8 = 0; n8 < N8; n8++)
                    mma16(c[m16][n8], af[cur][m16], bf[cur][n8]);
        }
    }

#pragma unroll
    for (int m16 = 0; m16 < M16; m16++) {
#pragma unroll
        for (int hh = 0; hh < 2; hh++) {
            int gr = m0 + warpM * 64 + m16 * 16 + hh * 8 + qid;
#pragma unroll
            for (int n8 = 0; n8 < N8; n8++) {
                int gcol = n0 + warpN * 64 + n8 * 8 + tq * 2;
                float v0 = c[m16][n8][hh * 2 + 0];
                float v1 = c[m16][n8][hh * 2 + 1];
                {
                    float2 b2 = *(const float2*)&bias[gcol];
                    v0 += b2.x; v1 += b2.y;
                }
                if (EPI == 1) { v0 = gelu_tanh(v0); v1 = gelu_tanh(v1); }
                if (EPI == 2) {
                    float2 g2 = *(const float2*)&mod[(size_t)(gr >> 10) * MODW + gate_ofs + gcol];
                    float2 r2 = *(const float2*)&resid[(size_t)gr * ldc + gcol];
                    v0 = r2.x + g2.x * v0;
                    v1 = r2.y + g2.y * v1;
                }
                OT* dst = &C[(size_t)gr * ldc + gcol];
                if (sizeof(OT) == 2) {
                    __half2 hv = __floats2half2_rn(v0, v1);
                    *(__half2*)dst = hv;
                } else {
                    *(float2*)dst = make_float2(v0, v1);
                }
            }
        }
    }
}

// ---------------------------------------------------------------------------
// Fused flash attention: 128-thr CTA / 64 q rows / 2-stage KV ring / 2 CTAs/SM.
// V via ldmatrix.trans from qkv16. Softmax exp via ex2.approx.f16x2; the
// f16x2 result doubles as the PV A-fragment. Dead q-tiles short-circuit.
// ---------------------------------------------------------------------------
#define FA_QOFF 0
#define FA_FOFF 9216
#define FA_KOFF 13312
#define FA_KST  18432
#define FA_VOFF 50176
#define FA_VST  18432
#define FA_SMEM 87040

__global__ __launch_bounds__(128, 2)
void fa_kernel(const __half* __restrict__ qkv,
               const float* __restrict__ fmask, const float* __restrict__ sumv,
               __half* __restrict__ attn) {
    extern __shared__ char dsm[];
    __shared__ float sred[4];
    __shared__ int s_nt;
    uint32_t sb = smem_u32(dsm);
    const float* smF = (const float*)(dsm + FA_FOFF);
    int tid = threadIdx.x, wid = tid >> 5, lane = tid & 31;
    int qid = lane >> 2, tq = lane & 3;
    int by = blockIdx.y;
    int b = by >> 4, h = by & 15;
    int q0 = blockIdx.x * 64;

    if (fmask[b * 1024 + q0] == 0.f) {
        const float* sv = sumv + by * 64;
        int gr0 = q0 + wid * 16 + qid;
        __half* o0 = attn + ((size_t)(b * 1024) + gr0) * 1024 + h * 64;
        __half* o1 = o0 + (size_t)8 * 1024;
#pragma unroll
        for (int t = 0; t < 8; t++) {
            float2 s2 = *(const float2*)&sv[8 * t + 2 * tq];
            __half2 hv = __floats2half2_rn(s2.x * (1.f / 1024.f), s2.y * (1.f / 1024.f));
            *(__half2*)(o0 + 8 * t + 2 * tq) = hv;
            *(__half2*)(o1 + 8 * t + 2 * tq) = hv;
        }
        return;
    }

    const __half* Qg = qkv + ((size_t)(b * 1024 + q0)) * 3072 + h * 64;
    const __half* Kg = qkv + ((size_t)(b * 1024)) * 3072 + 1024 + h * 64;
    const __half* Vg = qkv + ((size_t)(b * 1024)) * 3072 + 2048 + h * 64;

    auto loadKV = [&](int st, int kt) {
#pragma unroll
        for (int j = 0; j < 8; j++) {
            int i = tid + j * 128;
            int r = i >> 3, ch = i & 7;
            cp16(sb + FA_KOFF + st * FA_KST + r * 144 + ch * 16,
                 Kg + (size_t)(kt * 128 + r) * 3072 + ch * 8);
        }
#pragma unroll
        for (int j = 0; j < 8; j++) {
            int i = tid + j * 128;
            int r = i >> 3, ch = i & 7;
            cp16(sb + FA_VOFF + st * FA_VST + r * 144 + ch * 16,
                 Vg + (size_t)(kt * 128 + r) * 3072 + ch * 8);
        }
    };

#pragma unroll
    for (int j = 0; j < 4; j++) {
        int i = tid + j * 128;
        int r = i >> 3, ch = i & 7;
        cp16(sb + FA_QOFF + r * 144 + ch * 16, Qg + (size_t)r * 3072 + ch * 8);
    }
    cp16(sb + FA_FOFF + tid * 32, fmask + b * 1024 + tid * 8);
    cp16(sb + FA_FOFF + tid * 32 + 16, fmask + b * 1024 + tid * 8 + 4);
    loadKV(0, 0);
    cp_commit();

    int aRow = lane & 15, aCol = (lane >> 4) * 16;
    int bRow = (lane & 7) + ((lane >> 4) << 3), bCol = ((lane >> 3) & 1) * 16;
    int vRow = (lane & 7) + (((lane >> 3) & 1) << 3), vCol = (lane >> 4) * 16;
    int r0 = wid * 16;

    cp_wait<0>();
    __syncthreads();

    {
        float cnt = 0.f;
        float4 m4a = *(const float4*)(smF + tid * 8);
        float4 m4b = *(const float4*)(smF + tid * 8 + 4);
        cnt = (m4a.x != 0.f) + (m4a.y != 0.f) + (m4a.z != 0.f) + (m4a.w != 0.f)
            + (m4b.x != 0.f) + (m4b.y != 0.f) + (m4b.z != 0.f) + (m4b.w != 0.f);
#pragma unroll
        for (int o = 16; o > 0; o >>= 1) cnt += __shfl_down_sync(0xFFFFFFFFu, cnt, o);
        if (lane == 0) sred[wid] = cnt;
        __syncthreads();
        if (tid == 0) {
            float tot = sred[0] + sred[1] + sred[2] + sred[3];
            s_nt = ((int)(tot + 0.5f) + 127) >> 7;
        }
        __syncthreads();
    }
    int ntiles = s_nt;

    uint32_t qa[4][4];
#pragma unroll
    for (int ks = 0; ks < 4; ks++)
        ldsm4(qa[ks], sb + FA_QOFF + (r0 + aRow) * 144 + ks * 32 + aCol);

    float O[8][4];
#pragma unroll
    for (int t = 0; t < 8; t++)
#pragma unroll
        for (int q = 0; q < 4; q++) O[t][q] = 0.f;
    float m0 = -3.0e38f, m1 = -3.0e38f, l0 = 0.f, l1 = 0.f;
    const float L2E = 1.4426950408889634f;

    for (int kt = 0; kt < ntiles; kt++) {
        if (kt > 0) { cp_wait<0>(); __syncthreads(); }
        if (kt + 1 < ntiles) loadKV((kt + 1) & 1, kt + 1);
        cp_commit();

        uint32_t Ks = sb + FA_KOFF + (kt & 1) * FA_KST;
        uint32_t Vs = sb + FA_VOFF + (kt & 1) * FA_VST;

        // S = Q K^T
        float sc[16][4];
#pragma unroll
        for (int j = 0; j < 16; j++)
#pragma unroll
            for (int q = 0; q < 4; q++) sc[j][q] = 0.f;
#pragma unroll
        for (int ks = 0; ks < 4; ks++) {
            uint32_t kb[16][2];
#pragma unroll
            for (int p = 0; p < 8; p++) {
                uint32_t r4[4];
                ldsm4(r4, Ks + (16 * p + bRow) * 144 + ks * 32 + bCol);
                kb[2 * p][0] = r4[0]; kb[2 * p][1] = r4[1];
                kb[2 * p + 1][0] = r4[2]; kb[2 * p + 1][1] = r4[3];
            }
#pragma unroll
            for (int j = 0; j < 16; j++) mma16(sc[j], qa[ks], kb[j]);
        }

        bool mr0 = smF[q0 + r0 + qid] != 0.f;
        bool mr1 = smF[q0 + r0 + qid + 8] != 0.f;
#pragma unroll
        for (int j = 0; j < 16; j++) {
            int kvc = kt * 128 + 8 * j + 2 * tq;
            bool mk0 = smF[kvc] != 0.f;
            bool mk1 = smF[kvc + 1] != 0.f;
            sc[j][0] = (mr0 && mk0) ? sc[j][0] * 0.125f : -1e9f;
            sc[j][1] = (mr0 && mk1) ? sc[j][1] * 0.125f : -1e9f;
            sc[j][2] = (mr1 && mk0) ? sc[j][2] * 0.125f : -1e9f;
            sc[j][3] = (mr1 && mk1) ? sc[j][3] * 0.125f : -1e9f;
        }

        float mx0 = -3.0e38f, mx1 = -3.0e38f;
#pragma unroll
        for (int j = 0; j < 16; j++) {
            mx0 = fmaxf(mx0, fmaxf(sc[j][0], sc[j][1]));
            mx1 = fmaxf(mx1, fmaxf(sc[j][2], sc[j][3]));
        }
        mx0 = fmaxf(mx0, __shfl_xor_sync(0xFFFFFFFFu, mx0, 1));
        mx0 = fmaxf(mx0, __shfl_xor_sync(0xFFFFFFFFu, mx0, 2));
        mx1 = fmaxf(mx1, __shfl_xor_sync(0xFFFFFFFFu, mx1, 1));
        mx1 = fmaxf(mx1, __shfl_xor_sync(0xFFFFFFFFu, mx1, 2));
        float nm0 = fmaxf(m0, mx0), nm1 = fmaxf(m1, mx1);
        float cr0 = __expf(m0 - nm0), cr1 = __expf(m1 - nm1);
        m0 = nm0; m1 = nm1;

        // exp via f16x2 ex2 — result IS the PV fp16 fragment
        float mb0 = m0 * L2E, mb1 = m1 * L2E;
        float rs0 = 0.f, rs1 = 0.f;
        uint32_t pa[8][4];
#pragma unroll
        for (int j = 0; j < 16; j++) {
            uint32_t e0 = h2ex2(packh2(fmaf(sc[j][0], L2E, -mb0), fmaf(sc[j][1], L2E, -mb0)));
            uint32_t e1 = h2ex2(packh2(fmaf(sc[j][2], L2E, -mb1), fmaf(sc[j][3], L2E, -mb1)));
            pa[j >> 1][(j & 1) * 2 + 0] = e0;
            pa[j >> 1][(j & 1) * 2 + 1] = e1;
            float2 f0 = h2f2(e0), f1 = h2f2(e1);
            rs0 += f0.x + f0.y;
            rs1 += f1.x + f1.y;
        }
        rs0 += __shfl_xor_sync(0xFFFFFFFFu, rs0, 1);
        rs0 += __shfl_xor_sync(0xFFFFFFFFu, rs0, 2);
        rs1 += __shfl_xor_sync(0xFFFFFFFFu, rs1, 1);
        rs1 += __shfl_xor_sync(0xFFFFFFFFu, rs1, 2);
        l0 = l0 * cr0 + rs0;
        l1 = l1 * cr1 + rs1;
#pragma unroll
        for (int t = 0; t < 8; t++) {
            O[t][0] *= cr0; O[t][1] *= cr0;
            O[t][2] *= cr1; O[t][3] *= cr1;
        }

        // O += P V : V^T fragments via ldmatrix.trans of row-major V tile.
#pragma unroll
        for (int k = 0; k < 8; k++) {
            uint32_t vb[8][2];
#pragma unroll
            for (int p = 0; p < 4; p++) {
                uint32_t r4[4];
                ldsm4t(r4, Vs + (16 * k + vRow) * 144 + p * 32 + vCol);
                vb[2 * p][0] = r4[0]; vb[2 * p][1] = r4[1];
                vb[2 * p + 1][0] = r4[2]; vb[2 * p + 1][1] = r4[3];
            }
#pragma unroll
            for (int t = 0; t < 8; t++) mma16(O[t], pa[k], vb[t]);
        }
    }

    bool mr0 = smF[q0 + r0 + qid] != 0.f;
    bool mr1 = smF[q0 + r0 + qid + 8] != 0.f;
    float li0 = 1.f / l0, li1 = 1.f / l1;
    int gr0 = q0 + r0 + qid;
    __half* o0 = attn + ((size_t)(b * 1024) + gr0) * 1024 + h * 64;
    __half* o1 = o0 + (size_t)8 * 1024;
    const float* sv = sumv + by * 64;
#pragma unroll
    for (int t = 0; t < 8; t++) {
        float2 s2 = *(const float2*)&sv[8 * t + 2 * tq];
        float u0 = mr0 ? O[t][0] * li0 : s2.x * (1.f / 1024.f);
        float u1 = mr0 ? O[t][1] * li0 : s2.y * (1.f / 1024.f);
        float u2 = mr1 ? O[t][2] * li1 : s2.x * (1.f / 1024.f);
        float u3 = mr1 ? O[t][3] * li1 : s2.y * (1.f / 1024.f);
        *(__half2*)(o0 + 8 * t + 2 * tq) = __floats2half2_rn(u0, u1);
        *(__half2*)(o1 + 8 * t + 2 * tq) = __floats2half2_rn(u2, u3);
    }
}

// ---------------------------------------------------------------------------
// sumV reduction: one CTA per (b,h); 256 thr = 4 m-chunks x 64 d.
// ---------------------------------------------------------------------------
__global__ __launch_bounds__(256)
void sumv_kernel(const __half* __restrict__ qkv, float* __restrict__ sumv) {
    __shared__ float sh[256];
    int by = blockIdx.x;
    int b = by >> 4, h = by & 15;
    int tid = threadIdx.x;
    int d = tid & 63, mc = tid >> 6;
    const __half* Vg = qkv + (size_t)b * 1024 * 3072 + 2048 + h * 64 + d;
    float s = 0.f;
    for (int m = mc * 256; m < mc * 256 + 256; m++)
        s += __half2float(Vg[(size_t)m * 3072]);
    sh[tid] = s;
    __syncthreads();
    if (tid < 64)
        sumv[by * 64 + tid] = sh[tid] + sh[tid + 64] + sh[tid + 128] + sh[tid + 192];
}

// ---------------------------------------------------------------------------
// Merged weight conversion + prep + length accumulation
// ---------------------------------------------------------------------------
#define CV_Q 1572864
#define CV_P (CV_Q + 524288)
#define CV_F1 (CV_P + 2097152)
#define CV_TOT (CV_F1 + 2097152)

__global__ void cvt_all(const float* __restrict__ qkv_w, const float* __restrict__ proj_w,
                        const float* __restrict__ fc1_w, const float* __restrict__ fc2_w,
                        __half* __restrict__ o_qkv, __half* __restrict__ o_proj,
                        __half* __restrict__ o_fc1, __half* __restrict__ o_fc2,
                        const float* __restrict__ c, const void* __restrict__ mask,
                        float* __restrict__ silu_c, float* __restrict__ fmask,
                        int* __restrict__ lenq) {
    int i = blockIdx.x * blockDim.x + threadIdx.x;
    if (i < Bq * Cq) {
        float v = c[i];
        silu_c[i] = v / (1.0f + expf(-v));
        unsigned w0 = *(const unsigned*)mask;
        float mv;
        if (w0 == 0x3F800000u)        mv = ((const float*)mask)[i];
        else if (w0 == 0x01010101u)   mv = ((const unsigned char*)mask)[i] ? 1.f : 0.f;
        else                          mv = ((const int*)mask)[i] ? 1.f : 0.f;
        bool on = (mv != 0.f);
        fmask[i] = on ? 1.f : 0.f;
        if (on) atomicAdd(&lenq[i >> 10], 1);
    }
    if (i >= CV_TOT) return;
    const float* s; __half* d; int off;
    if (i < CV_Q)        { s = qkv_w;  d = o_qkv;  off = i; }
    else if (i < CV_P)   { s = proj_w; d = o_proj; off = i - CV_Q; }
    else if (i < CV_F1)  { s = fc1_w;  d = o_fc1;  off = i - CV_P; }
    else                 { s = fc2_w;  d = o_fc2;  off = i - CV_F1; }
    float2 v = *(const float2*)&s[off * 2];
    *(__half2*)&d[off * 2] = __floats2half2_rn(v.x, v.y);
}

// ---------------------------------------------------------------------------
// fp32 SGEMM for the tiny ada GEMM (M=8)
// ---------------------------------------------------------------------------
__global__ __launch_bounds__(256)
void sgemm_ada(const float* __restrict__ A, const float* __restrict__ B,
               const float* __restrict__ bias, float* __restrict__ C,
               int M, int N, int K) {
    __shared__ float As[16][128];
    __shared__ float Bs[16][128];
    int tid = threadIdx.x;
    int tx = tid & 15, ty = tid >> 4;
    int m0 = blockIdx.y * 128, n0 = blockIdx.x * 128;
    float acc[8][8];
#pragma unroll
    for (int i = 0; i < 8; i++)
#pragma unroll
        for (int j = 0; j < 8; j++) acc[i][j] = 0.f;
    int lr = tid >> 2, lk4 = (tid & 3) * 4;
    for (int k0 = 0; k0 < K; k0 += 16) {
#pragma unroll
        for (int s = 0; s < 2; s++) {
            int rr = lr + s * 64;
            int gm = m0 + rr;
            float4 va = make_float4(0.f, 0.f, 0.f, 0.f);
            if (gm < M) va = *(const float4*)&A[(size_t)gm * K + k0 + lk4];
            As[lk4 + 0][rr] = va.x; As[lk4 + 1][rr] = va.y;
            As[lk4 + 2][rr] = va.z; As[lk4 + 3][rr] = va.w;
            float4 vb = *(const float4*)&B[(size_t)(n0 + rr) * K + k0 + lk4];
            Bs[lk4 + 0][rr] = vb.x; Bs[lk4 + 1][rr] = vb.y;
            Bs[lk4 + 2][rr] = vb.z; Bs[lk4 + 3][rr] = vb.w;
        }
        __syncthreads();
#pragma unroll
        for (int kk = 0; kk < 16; kk++) {
            float a[8], b[8];
            *(float4*)&a[0] = *(const float4*)&As[kk][ty * 8];
            *(float4*)&a[4] = *(const float4*)&As[kk][ty * 8 + 4];
            *(float4*)&b[0] = *(const float4*)&Bs[kk][tx * 8];
            *(float4*)&b[4] = *(const float4*)&Bs[kk][tx * 8 + 4];
#pragma unroll
            for (int i = 0; i < 8; i++)
#pragma unroll
                for (int j = 0; j < 8; j++) acc[i][j] += a[i] * b[j];
        }
        __syncthreads();
    }
#pragma unroll
    for (int i = 0; i < 8; i++) {
        int row = m0 + ty * 8 + i;
        if (row >= M) continue;
#pragma unroll
        for (int j = 0; j < 8; j++) {
            int col = n0 + tx * 8 + j;
            C[(size_t)row * N + col] = acc[i][j] + bias[col];
        }
    }
}

// ---------------------------------------------------------------------------
// LayerNorm + modulate, writes fp16
// ---------------------------------------------------------------------------
__global__ __launch_bounds__(256)
void ln_mod_kernel(const float* __restrict__ x, const float* __restrict__ mod,
                   int shift_ofs, int scale_ofs, __half* __restrict__ out) {
    int row = blockIdx.x;
    int b = row >> 10;
    const float* xr = x + (size_t)row * Cq;
    int tid = threadIdx.x;
    float v[4];
    float s = 0.f, s2 = 0.f;
#pragma unroll
    for (int t = 0; t < 4; t++) {
        float u = xr[tid + t * 256];
        v[t] = u; s += u; s2 += u * u;
    }
    __shared__ float sh[18];
#pragma unroll
    for (int o = 16; o > 0; o >>= 1) {
        s  += __shfl_down_sync(0xFFFFFFFFu, s, o);
        s2 += __shfl_down_sync(0xFFFFFFFFu, s2, o);
    }
    int wid = tid >> 5, lane = tid & 31;
    if (lane == 0) { sh[wid] = s; sh[wid + 8] = s2; }
    __syncthreads();
    if (tid == 0) {
        float a = 0.f, b2 = 0.f;
        for (int w = 0; w < 8; w++) { a += sh[w]; b2 += sh[w + 8]; }
        float mu = a * (1.f / 1024.f);
        float var = b2 * (1.f / 1024.f) - mu * mu;
        sh[16] = mu;
        sh[17] = rsqrtf(var + 1e-6f);
    }
    __syncthreads();
    float mu = sh[16], rs = sh[17];
    const float* mb = mod + (size_t)b * MODW;
    __half* orow = out + (size_t)row * Cq;
#pragma unroll
    for (int t = 0; t < 4; t++) {
        int cidx = tid + t * 256;
        float r = (v[t] - mu) * rs * (1.f + mb[scale_ofs + cidx]) + mb[shift_ofs + cidx];
        orow[cidx] = __float2half_rn(r);
    }
}

// ---------------------------------------------------------------------------
// launch
// ---------------------------------------------------------------------------
extern "C" void kernel_launch(void* const* d_in, const int* in_sizes, int n_in,
                              void* d_out, int out_size) {
    (void)in_sizes; (void)n_in; (void)out_size;
    const float* x      = (const float*)d_in[0];
    const float* c      = (const float*)d_in[1];
    const void*  pmask  = d_in[2];
    const float* qkv_w  = (const float*)d_in[3];
    const float* qkv_b  = (const float*)d_in[4];
    const float* proj_w = (const float*)d_in[5];
    const float* proj_b = (const float*)d_in[6];
    const float* fc1_w  = (const float*)d_in[7];
    const float* fc1_b  = (const float*)d_in[8];
    const float* fc2_w  = (const float*)d_in[9];
    const float* fc2_b  = (const float*)d_in[10];
    const float* ada_w  = (const float*)d_in[11];
    const float* ada_b  = (const float*)d_in[12];
    float* out = (float*)d_out;

    void *p;
    cudaGetSymbolAddress(&p, g_silu_c);  float*  silu_c = (float*)p;
    cudaGetSymbolAddress(&p, g_mod);     float*  mod    = (float*)p;
    cudaGetSymbolAddress(&p, g_fmask);   float*  fmask  = (float*)p;
    cudaGetSymbolAddress(&p, g_lenq);    int*    lenq   = (int*)p;
    cudaGetSymbolAddress(&p, g_sumv);    float*  sumv   = (float*)p;
    cudaGetSymbolAddress(&p, g_x2);      float*  x2     = (float*)p;
    cudaGetSymbolAddress(&p, g_h16);     __half* h16    = (__half*)p;
    cudaGetSymbolAddress(&p, g_qkv16);   __half* qkv16  = (__half*)p;
    cudaGetSymbolAddress(&p, g_attn16);  __half* attn16 = (__half*)p;
    cudaGetSymbolAddress(&p, g_t16);     __half* t16    = (__half*)p;
    cudaGetSymbolAddress(&p, g_qkvw16);  __half* qkvw16 = (__half*)p;
    cudaGetSymbolAddress(&p, g_projw16); __half* projw16 = (__half*)p;
    cudaGetSymbolAddress(&p, g_fc1w16);  __half* fc1w16 = (__half*)p;
    cudaGetSymbolAddress(&p, g_fc2w16);  __half* fc2w16 = (__half*)p;

    const int SMEMG = STAGES * 2 * 128 * ROWB;   // 110592
    cudaFuncSetAttribute((const void*)gemm_h<0, 1, __half>, cudaFuncAttributeMaxDynamicSharedMemorySize, SMEMG);
    cudaFuncSetAttribute((const void*)gemm_h<1, 0, __half>, cudaFuncAttributeMaxDynamicSharedMemorySize, SMEMG);
    cudaFuncSetAttribute((const void*)gemm_h<2, 0, float>,  cudaFuncAttributeMaxDynamicSharedMemorySize, SMEMG);
    cudaFuncSetAttribute((const void*)fa_kernel, cudaFuncAttributeMaxDynamicSharedMemorySize, FA_SMEM);

    cudaMemsetAsync(lenq, 0, Bq * sizeof(int));

    cvt_all<<<(CV_TOT + 255) / 256, 256>>>(qkv_w, proj_w, fc1_w, fc2_w,
                                           qkvw16, projw16, fc1w16, fc2w16,
                                           c, pmask, silu_c, fmask, lenq);

    sgemm_ada<<<dim3(MODW / 128, 1), 256>>>(silu_c, ada_w, ada_b, mod, Bq, MODW, Cq);

    ln_mod_kernel<<<TOK, 256>>>(x, mod, 0, Cq, h16);

    // qkv = h @ qkv_w^T + b   [8192, 3072]  (Q/K padded-row tiles skipped)
    gemm_h<0, 1, __half><<<dim3(24, 64), 128, SMEMG>>>(
        h16, qkvw16, qkv_b, nullptr, nullptr, 0, qkv16, lenq, 1024, 1024, 3072, 1024);

    sumv_kernel<<<128, 256>>>(qkv16, sumv);

    // fused flash attention
    fa_kernel<<<dim3(16, 128), 128, FA_SMEM>>>(qkv16, fmask, sumv, attn16);

    // x2 = x + gate_msa * (attn @ proj_w^T + b)
    gemm_h<2, 0, float><<<dim3(8, 64), 128, SMEMG>>>(
        attn16, projw16, proj_b, x, mod, 2 * Cq, x2, nullptr, 1024, 1024, 1024, 1024);

    ln_mod_kernel<<<TOK, 256>>>(x2, mod, 3 * Cq, 4 * Cq, h16);

    // t = gelu(h @ fc1_w^T + b)   [8192, 4096]
    gemm_h<1, 0, __half><<<dim3(32, 64), 128, SMEMG>>>(
        h16, fc1w16, fc1_b, nullptr, nullptr, 0, t16, nullptr, 1024, 1024, 4096, 1024);

    // out = x2 + gate_mlp * (t @ fc2_w^T + b)
    gemm_h<2, 0, float><<<dim3(8, 64), 128, SMEMG>>>(
        t16, fc2w16, fc2_b, x2, mod, 5 * Cq, out, nullptr, 4096, 4096, 1024, 4096);
}